// round 1
// baseline (speedup 1.0000x reference)
#include <cuda_runtime.h>
#include <cstdint>

#define Nn 10000
#define Ee 160000
#define Cc 64
#define PI_F 3.14159265358979f

// Scratch (global __device__ arrays — no allocation in kernel_launch)
__device__ float g_Xn  [Nn * Cc * 9];          // normalized input tensors, [n][c][9]
__device__ float g_feat[Nn * Cc * 12];         // mixed compressed node feats, [n][c][12] (9 used)
__device__ float g_msg [Nn * Cc * 12];         // compressed message accumulators
__device__ float g_a   [(size_t)Ee * Cc * 4];  // edge MLP output, [e][c][4] = {aI,aA,aS,pad}

__device__ __forceinline__ float silu_f(float x) {
    return x / (1.f + __expf(-x));
}

__device__ __forceinline__ void red4(float* p, float a, float b, float c, float d) {
    asm volatile("red.global.add.v4.f32 [%0], {%1,%2,%3,%4};"
                 :: "l"(p), "f"(a), "f"(b), "f"(c), "f"(d) : "memory");
}
__device__ __forceinline__ void red1(float* p, float a) {
    asm volatile("red.global.add.f32 [%0], %1;" :: "l"(p), "f"(a) : "memory");
}

// Reconstruct full 3x3 from compressed comps {lam, a01,a02,a12, s00,s11,s01,s02,s12}
__device__ __forceinline__ void reconstruct(float F[9], const float c[9]) {
    float lam = c[0], a01 = c[1], a02 = c[2], a12 = c[3];
    float s00 = c[4], s11 = c[5], s01 = c[6], s02 = c[7], s12 = c[8];
    float s22 = -(s00 + s11);
    F[0] = lam + s00;  F[1] =  a01 + s01; F[2] =  a02 + s02;
    F[3] = -a01 + s01; F[4] = lam + s11;  F[5] =  a12 + s12;
    F[6] = -a02 + s02; F[7] = -a12 + s12; F[8] = lam + s22;
}

__device__ __forceinline__ void mm3(float C[9], const float A[9], const float B[9]) {
    #pragma unroll
    for (int i = 0; i < 3; i++)
        #pragma unroll
        for (int j = 0; j < 3; j++) {
            float acc = 0.f;
            #pragma unroll
            for (int k = 0; k < 3; k++) acc += A[i*3+k] * B[k*3+j];
            C[i*3+j] = acc;
        }
}

// ---------------------------------------------------------------------------
// K0: zero message accumulators
// ---------------------------------------------------------------------------
__global__ void k_zero_msg() {
    int i = blockIdx.x * 256 + threadIdx.x;
    if (i < Nn * Cc * 12) g_msg[i] = 0.f;
}

// ---------------------------------------------------------------------------
// K1: node prep — normalize, store Xn, decompose, channel-mix with Wt[0..2]
// Block handles 8 nodes with 256 threads.
// ---------------------------------------------------------------------------
__global__ __launch_bounds__(256) void k_nodeprep(const float* __restrict__ X,
                                                  const float* __restrict__ Wt) {
    __shared__ float s_raw[8][9][64];
    int t = threadIdx.x;
    int nb = blockIdx.x * 8;

    // Phase A: per (node,c) normalize + decompose (512 pairs, 2 iters)
    #pragma unroll
    for (int it = 0; it < 2; it++) {
        int p = t + it * 256;
        int s = p >> 6, c = p & 63;
        int n = nb + s;
        const float* xp = X + (size_t)(n * 64 + c) * 9;
        float x[9];
        float n2 = 0.f;
        #pragma unroll
        for (int i = 0; i < 9; i++) { x[i] = xp[i]; n2 += x[i] * x[i]; }
        float inv = 1.f / (n2 + 1.f);
        float* xo = g_Xn + (size_t)(n * 64 + c) * 9;
        #pragma unroll
        for (int i = 0; i < 9; i++) { x[i] *= inv; xo[i] = x[i]; }
        float lam = (x[0] + x[4] + x[8]) * (1.f / 3.f);
        s_raw[s][0][c] = lam;
        s_raw[s][1][c] = 0.5f * (x[1] - x[3]);
        s_raw[s][2][c] = 0.5f * (x[2] - x[6]);
        s_raw[s][3][c] = 0.5f * (x[5] - x[7]);
        s_raw[s][4][c] = x[0] - lam;
        s_raw[s][5][c] = x[4] - lam;
        s_raw[s][6][c] = 0.5f * (x[1] + x[3]);
        s_raw[s][7][c] = 0.5f * (x[2] + x[6]);
        s_raw[s][8][c] = 0.5f * (x[5] + x[7]);
    }
    __syncthreads();

    // Phase B: channel mixing. thread (g,l): g handles nodes {2g, 2g+1}, output channel l
    int l = t & 63, g = t >> 6;
    const float* rA0 = &s_raw[g * 2][0][0];
    const float* rB0 = &s_raw[g * 2 + 1][0][0];
    int n0 = nb + g * 2, n1 = n0 + 1;
    #pragma unroll
    for (int comp = 0; comp < 9; comp++) {
        int sel = (comp == 0) ? 0 : ((comp < 4) ? 1 : 2);
        const float* w = Wt + sel * 4096 + l;
        const float* rA = rA0 + comp * 64;
        const float* rB = rB0 + comp * 64;
        float a0 = 0.f, a1 = 0.f;
        #pragma unroll 16
        for (int k = 0; k < 64; k++) {
            float wv = __ldg(w + k * 64);
            a0 += rA[k] * wv;
            a1 += rB[k] * wv;
        }
        g_feat[((size_t)n0 * 64 + l) * 12 + comp] = a0;
        g_feat[((size_t)n1 * 64 + l) * 12 + comp] = a1;
    }
}

// ---------------------------------------------------------------------------
// K2: fused edge MLP: attr[E,32] -> silu(.@W1) -> silu(.@W2) -> silu(.@W3) * Cw
// Block: 32 edges, 256 threads. Static smem: 4+8+16+12 = 40 KB.
// Output: g_a[e][c][4] = {out[3c], out[3c+1], out[3c+2], 0}
// ---------------------------------------------------------------------------
__global__ __launch_bounds__(256) void k_edge_mlp(
    const float* __restrict__ attr, const float* __restrict__ ew,
    const float* __restrict__ W1, const float* __restrict__ b1,
    const float* __restrict__ W2, const float* __restrict__ b2,
    const float* __restrict__ W3, const float* __restrict__ b3) {
    __shared__ __align__(16) float s_attr[32 * 32];
    __shared__ __align__(16) float s_h1[32 * 64];
    __shared__ __align__(16) float s_h2[32 * 128];
    __shared__ __align__(16) float s_w[3072];

    int t = threadIdx.x;
    int e0 = blockIdx.x * 32;
    int e = t >> 3;           // local edge 0..31
    int q = t & 7;

    for (int i = t; i < 1024; i += 256) s_attr[i] = attr[(size_t)e0 * 32 + i];
    for (int i = t; i < 2048; i += 256) s_w[i] = W1[i];
    __syncthreads();

    // ---- layer 1: 32 -> 64 ----
    {
        int jb = q * 8;
        float acc[8];
        #pragma unroll
        for (int j = 0; j < 8; j++) acc[j] = __ldg(b1 + jb + j);
        #pragma unroll 4
        for (int k = 0; k < 32; k++) {
            float av = s_attr[e * 32 + k];
            const float4* wp = (const float4*)(s_w + k * 64 + jb);
            float4 w0 = wp[0], w1 = wp[1];
            acc[0] += av * w0.x; acc[1] += av * w0.y; acc[2] += av * w0.z; acc[3] += av * w0.w;
            acc[4] += av * w1.x; acc[5] += av * w1.y; acc[6] += av * w1.z; acc[7] += av * w1.w;
        }
        #pragma unroll
        for (int j = 0; j < 8; j++) s_h1[e * 64 + jb + j] = silu_f(acc[j]);
    }
    __syncthreads();

    // ---- layer 2: 64 -> 128, weight chunks of k=16 ----
    {
        int jb = q * 16;
        float acc[16];
        #pragma unroll
        for (int j = 0; j < 16; j++) acc[j] = __ldg(b2 + jb + j);
        for (int cc = 0; cc < 4; cc++) {
            for (int i = t; i < 2048; i += 256) s_w[i] = W2[cc * 2048 + i];
            __syncthreads();
            #pragma unroll 4
            for (int k = 0; k < 16; k++) {
                float hv = s_h1[e * 64 + cc * 16 + k];
                const float4* wp = (const float4*)(s_w + k * 128 + jb);
                float4 w0 = wp[0], w1 = wp[1], w2 = wp[2], w3 = wp[3];
                acc[0]  += hv * w0.x; acc[1]  += hv * w0.y; acc[2]  += hv * w0.z; acc[3]  += hv * w0.w;
                acc[4]  += hv * w1.x; acc[5]  += hv * w1.y; acc[6]  += hv * w1.z; acc[7]  += hv * w1.w;
                acc[8]  += hv * w2.x; acc[9]  += hv * w2.y; acc[10] += hv * w2.z; acc[11] += hv * w2.w;
                acc[12] += hv * w3.x; acc[13] += hv * w3.y; acc[14] += hv * w3.z; acc[15] += hv * w3.w;
            }
            __syncthreads();
        }
        #pragma unroll
        for (int j = 0; j < 16; j++) s_h2[e * 128 + jb + j] = silu_f(acc[j]);
    }
    __syncthreads();

    // ---- layer 3: 128 -> 192, weight chunks of k=16 ----
    {
        int jb = q * 24;
        float acc[24];
        #pragma unroll
        for (int j = 0; j < 24; j++) acc[j] = __ldg(b3 + jb + j);
        for (int cc = 0; cc < 8; cc++) {
            for (int i = t; i < 3072; i += 256) s_w[i] = W3[cc * 3072 + i];
            __syncthreads();
            #pragma unroll 2
            for (int k = 0; k < 16; k++) {
                float hv = s_h2[e * 128 + cc * 16 + k];
                const float4* wp = (const float4*)(s_w + k * 192 + jb);
                #pragma unroll
                for (int m = 0; m < 6; m++) {
                    float4 wv = wp[m];
                    acc[m*4+0] += hv * wv.x; acc[m*4+1] += hv * wv.y;
                    acc[m*4+2] += hv * wv.z; acc[m*4+3] += hv * wv.w;
                }
            }
            __syncthreads();
        }
        float w = __ldg(ew + e0 + e);
        float cw = 0.5f * (__cosf(w * (PI_F / 5.0f)) + 1.0f);
        cw = (w < 5.0f) ? cw : 0.0f;
        #pragma unroll
        for (int m = 0; m < 24; m += 3) {
            int o = jb + m;
            int c = o / 3;           // jb divisible by 3
            float4 v;
            v.x = silu_f(acc[m])     * cw;
            v.y = silu_f(acc[m + 1]) * cw;
            v.z = silu_f(acc[m + 2]) * cw;
            v.w = 0.f;
            *(float4*)(g_a + ((size_t)(e0 + e) * 64 + c) * 4) = v;
        }
    }
}

// ---------------------------------------------------------------------------
// K3: message passing. Thread per (edge, channel). Gather compressed feats of
// dst, scale by a[e][c][{0,1,2}], vector-RED into msg[src].
// ---------------------------------------------------------------------------
__global__ __launch_bounds__(256) void k_message(const int* __restrict__ ei) {
    int idx = blockIdx.x * 256 + threadIdx.x;
    int e = idx >> 6, c = idx & 63;
    int src = __ldg(ei + e);
    int dst = __ldg(ei + Ee + e);
    float4 av = *(const float4*)(g_a + ((size_t)e * 64 + c) * 4);
    const float4* f = (const float4*)(g_feat + ((size_t)dst * 64 + c) * 12);
    float4 f0 = f[0], f1 = f[1];
    float  f8 = ((const float*)f)[8];
    float* b = g_msg + ((size_t)src * 64 + c) * 12;
    red4(b,     av.x * f0.x, av.y * f0.y, av.y * f0.z, av.y * f0.w);
    red4(b + 4, av.z * f1.x, av.z * f1.y, av.z * f1.z, av.z * f1.w);
    red1(b + 8, av.z * f8);
}

// ---------------------------------------------------------------------------
// K4: finalize. M = msg@Y + Y@msg, decompose, /(|M|^2+1), mix Wt[3..5],
// out = Xn + dX + dX@dX. Block: 8 nodes, 256 threads.
// ---------------------------------------------------------------------------
__global__ __launch_bounds__(256) void k_finalize(const float* __restrict__ Wt,
                                                  float* __restrict__ out) {
    __shared__ float s_raw[8][9][64];
    __shared__ float s_dx[8][9][64];
    int t = threadIdx.x;
    int nb = blockIdx.x * 8;

    #pragma unroll
    for (int it = 0; it < 2; it++) {
        int p = t + it * 256;
        int s = p >> 6, c = p & 63;
        int n = nb + s;
        const float* mp = g_msg + ((size_t)n * 64 + c) * 12;
        const float* fp = g_feat + ((size_t)n * 64 + c) * 12;
        float mc[9], fc[9];
        #pragma unroll
        for (int i = 0; i < 9; i++) { mc[i] = mp[i]; fc[i] = fp[i]; }
        float Mg[9], Y[9];
        reconstruct(Mg, mc);
        reconstruct(Y, fc);
        float M1[9], M2[9], M[9];
        mm3(M1, Mg, Y);
        mm3(M2, Y, Mg);
        float nrm = 0.f;
        #pragma unroll
        for (int i = 0; i < 9; i++) { M[i] = M1[i] + M2[i]; nrm += M[i] * M[i]; }
        float inv = 1.f / (nrm + 1.f);
        float lam = (M[0] + M[4] + M[8]) * (1.f / 3.f);
        s_raw[s][0][c] = lam * inv;
        s_raw[s][1][c] = 0.5f * (M[1] - M[3]) * inv;
        s_raw[s][2][c] = 0.5f * (M[2] - M[6]) * inv;
        s_raw[s][3][c] = 0.5f * (M[5] - M[7]) * inv;
        s_raw[s][4][c] = (M[0] - lam) * inv;
        s_raw[s][5][c] = (M[4] - lam) * inv;
        s_raw[s][6][c] = 0.5f * (M[1] + M[3]) * inv;
        s_raw[s][7][c] = 0.5f * (M[2] + M[6]) * inv;
        s_raw[s][8][c] = 0.5f * (M[5] + M[7]) * inv;
    }
    __syncthreads();

    // channel mixing with Wt[3..5]
    {
        int l = t & 63, g = t >> 6;
        const float* rA0 = &s_raw[g * 2][0][0];
        const float* rB0 = &s_raw[g * 2 + 1][0][0];
        #pragma unroll
        for (int comp = 0; comp < 9; comp++) {
            int sel = 3 + ((comp == 0) ? 0 : ((comp < 4) ? 1 : 2));
            const float* w = Wt + sel * 4096 + l;
            const float* rA = rA0 + comp * 64;
            const float* rB = rB0 + comp * 64;
            float a0 = 0.f, a1 = 0.f;
            #pragma unroll 16
            for (int k = 0; k < 64; k++) {
                float wv = __ldg(w + k * 64);
                a0 += rA[k] * wv;
                a1 += rB[k] * wv;
            }
            s_dx[g * 2][comp][l] = a0;
            s_dx[g * 2 + 1][comp][l] = a1;
        }
    }
    __syncthreads();

    #pragma unroll
    for (int it = 0; it < 2; it++) {
        int p = t + it * 256;
        int s = p >> 6, c = p & 63;
        int n = nb + s;
        float dc[9];
        #pragma unroll
        for (int i = 0; i < 9; i++) dc[i] = s_dx[s][i][c];
        float D[9];
        reconstruct(D, dc);
        float DD[9];
        mm3(DD, D, D);
        const float* xn = g_Xn + ((size_t)n * 64 + c) * 9;
        float* op = out + ((size_t)n * 64 + c) * 9;
        #pragma unroll
        for (int i = 0; i < 9; i++) op[i] = xn[i] + D[i] + DD[i];
    }
}

// ---------------------------------------------------------------------------
extern "C" void kernel_launch(void* const* d_in, const int* in_sizes, int n_in,
                              void* d_out, int out_size) {
    const float* X    = (const float*)d_in[0];
    const int*   ei   = (const int*)  d_in[1];
    const float* ew   = (const float*)d_in[2];
    const float* attr = (const float*)d_in[3];
    const float* W1   = (const float*)d_in[4];
    const float* b1   = (const float*)d_in[5];
    const float* W2   = (const float*)d_in[6];
    const float* b2   = (const float*)d_in[7];
    const float* W3   = (const float*)d_in[8];
    const float* b3   = (const float*)d_in[9];
    const float* Wt   = (const float*)d_in[10];
    float* out = (float*)d_out;

    k_zero_msg<<<(Nn * Cc * 12 + 255) / 256, 256>>>();
    k_nodeprep<<<Nn / 8, 256>>>(X, Wt);
    k_edge_mlp<<<Ee / 32, 256>>>(attr, ew, W1, b1, W2, b2, W3, b3);
    k_message<<<(Ee * Cc) / 256, 256>>>(ei);
    k_finalize<<<Nn / 8, 256>>>(Wt, out);
}

// round 5
// speedup vs baseline: 2.3927x; 2.3927x over previous
#include <cuda_runtime.h>
#include <cstdint>

#define Nn 10000
#define Ee 160000
#define Cc 64
#define PI_F 3.14159265358979f

// Scratch (global __device__ arrays)
__device__ float g_Xn  [Nn * Cc * 9];           // normalized input tensors, [n][c][9]
__device__ float g_feat[Nn * Cc * 12];          // mixed compressed node feats, [n][c][12] (9 used)
__device__ float g_msg [Nn * Cc * 12];          // compressed message accumulators
__device__ float g_a   [(size_t)Ee * 192];      // edge MLP output, [e][192]

__device__ __forceinline__ float silu_f(float x) {
    return x / (1.f + __expf(-x));
}

__device__ __forceinline__ void red4(float* p, float a, float b, float c, float d) {
    asm volatile("red.global.add.v4.f32 [%0], {%1,%2,%3,%4};"
                 :: "l"(p), "f"(a), "f"(b), "f"(c), "f"(d) : "memory");
}
__device__ __forceinline__ void red1(float* p, float a) {
    asm volatile("red.global.add.f32 [%0], %1;" :: "l"(p), "f"(a) : "memory");
}

__device__ __forceinline__ void reconstruct(float F[9], const float c[9]) {
    float lam = c[0], a01 = c[1], a02 = c[2], a12 = c[3];
    float s00 = c[4], s11 = c[5], s01 = c[6], s02 = c[7], s12 = c[8];
    float s22 = -(s00 + s11);
    F[0] = lam + s00;  F[1] =  a01 + s01; F[2] =  a02 + s02;
    F[3] = -a01 + s01; F[4] = lam + s11;  F[5] =  a12 + s12;
    F[6] = -a02 + s02; F[7] = -a12 + s12; F[8] = lam + s22;
}

__device__ __forceinline__ void mm3(float C[9], const float A[9], const float B[9]) {
    #pragma unroll
    for (int i = 0; i < 3; i++)
        #pragma unroll
        for (int j = 0; j < 3; j++) {
            float acc = 0.f;
            #pragma unroll
            for (int k = 0; k < 3; k++) acc += A[i*3+k] * B[k*3+j];
            C[i*3+j] = acc;
        }
}

__device__ __forceinline__ void fma4(float4& acc, float s, const float4& v) {
    acc.x = fmaf(s, v.x, acc.x);
    acc.y = fmaf(s, v.y, acc.y);
    acc.z = fmaf(s, v.z, acc.z);
    acc.w = fmaf(s, v.w, acc.w);
}

// ---------------------------------------------------------------------------
// K0: zero message accumulators
// ---------------------------------------------------------------------------
__global__ void k_zero_msg() {
    int i = blockIdx.x * 256 + threadIdx.x;
    if (i < Nn * Cc * 12) g_msg[i] = 0.f;
}

// ---------------------------------------------------------------------------
// K1: node prep — 16 nodes/block, Wt[0..2] staged in smem.
// dyn smem: 12288 (weights) + 16*9*64 (raw) = 21504 floats = 84 KB
// ---------------------------------------------------------------------------
__global__ __launch_bounds__(256) void k_nodeprep(const float* __restrict__ X,
                                                  const float* __restrict__ Wt) {
    extern __shared__ float sm[];
    float* sw   = sm;            // 3 * 4096
    float* sraw = sm + 12288;    // [16 nodes][9 comps][64 ch]
    int t = threadIdx.x;
    int nb = blockIdx.x * 16;

    for (int i = t; i < 3072; i += 256)
        ((float4*)sw)[i] = ((const float4*)Wt)[i];

    #pragma unroll
    for (int it = 0; it < 4; it++) {
        int p = t + it * 256;
        int s = p >> 6, c = p & 63;
        int n = nb + s;
        const float* xp = X + (size_t)(n * 64 + c) * 9;
        float x[9]; float n2 = 0.f;
        #pragma unroll
        for (int i = 0; i < 9; i++) { x[i] = xp[i]; n2 += x[i] * x[i]; }
        float inv = 1.f / (n2 + 1.f);
        float* xo = g_Xn + (size_t)(n * 64 + c) * 9;
        #pragma unroll
        for (int i = 0; i < 9; i++) { x[i] *= inv; xo[i] = x[i]; }
        float lam = (x[0] + x[4] + x[8]) * (1.f / 3.f);
        float* r = sraw + (s * 9) * 64 + c;
        r[0*64] = lam;
        r[1*64] = 0.5f * (x[1] - x[3]);
        r[2*64] = 0.5f * (x[2] - x[6]);
        r[3*64] = 0.5f * (x[5] - x[7]);
        r[4*64] = x[0] - lam;
        r[5*64] = x[4] - lam;
        r[6*64] = 0.5f * (x[1] + x[3]);
        r[7*64] = 0.5f * (x[2] + x[6]);
        r[8*64] = 0.5f * (x[5] + x[7]);
    }
    __syncthreads();

    int l = t & 63, g = t >> 6;           // g: 4 nodes each
    #pragma unroll
    for (int comp = 0; comp < 9; comp++) {
        int sel = (comp == 0) ? 0 : ((comp < 4) ? 1 : 2);
        const float* w = sw + sel * 4096 + l;
        float a0 = 0.f, a1 = 0.f, a2 = 0.f, a3 = 0.f;
        const float* r0 = sraw + ((g*4 + 0) * 9 + comp) * 64;
        const float* r1 = sraw + ((g*4 + 1) * 9 + comp) * 64;
        const float* r2 = sraw + ((g*4 + 2) * 9 + comp) * 64;
        const float* r3 = sraw + ((g*4 + 3) * 9 + comp) * 64;
        #pragma unroll 16
        for (int k = 0; k < 64; k++) {
            float wv = w[k * 64];
            a0 = fmaf(r0[k], wv, a0);
            a1 = fmaf(r1[k], wv, a1);
            a2 = fmaf(r2[k], wv, a2);
            a3 = fmaf(r3[k], wv, a3);
        }
        int n0 = nb + g * 4;
        g_feat[((size_t)(n0+0) * 64 + l) * 12 + comp] = a0;
        g_feat[((size_t)(n0+1) * 64 + l) * 12 + comp] = a1;
        g_feat[((size_t)(n0+2) * 64 + l) * 12 + comp] = a2;
        g_feat[((size_t)(n0+3) * 64 + l) * 12 + comp] = a3;
    }
}

// ---------------------------------------------------------------------------
// K2: fused edge MLP, register-tiled. 64 edges/block, 256 threads,
// all weights resident in smem. Thread tile: 4 edges x {4,8,12} outputs.
// smem floats: W1 2048 | b1 64 | W2 8192 | b2 128 | W3 24576 | b3 192
//              attrT 32*68 | h1T 64*68 | h2T 128*68   total 50432 (197 KB)
// ---------------------------------------------------------------------------
#define OW1 0
#define OB1 2048
#define OW2 2112
#define OB2 10304
#define OW3 10432
#define OB3 35008
#define OAT 35200
#define OH1 37376
#define OH2 41728
#define SM_EDGE_TOT 50432

__global__ __launch_bounds__(256) void k_edge_mlp(
    const float* __restrict__ attr, const float* __restrict__ ew,
    const float* __restrict__ W1, const float* __restrict__ b1,
    const float* __restrict__ W2, const float* __restrict__ b2,
    const float* __restrict__ W3, const float* __restrict__ b3) {
    extern __shared__ float sm[];
    int t = threadIdx.x;
    int e0 = blockIdx.x * 64;

    // stage weights + biases
    for (int i = t; i < 512;  i += 256) ((float4*)(sm + OW1))[i] = ((const float4*)W1)[i];
    for (int i = t; i < 2048; i += 256) ((float4*)(sm + OW2))[i] = ((const float4*)W2)[i];
    for (int i = t; i < 6144; i += 256) ((float4*)(sm + OW3))[i] = ((const float4*)W3)[i];
    if (t < 64)  sm[OB1 + t] = b1[t];
    if (t < 128) sm[OB2 + t] = b2[t];
    if (t < 192) sm[OB3 + t] = b3[t];
    // stage attr transposed: attrT[k][e], pitch 68
    for (int i = t; i < 2048; i += 256) {
        int e = i >> 5, k = i & 31;
        sm[OAT + k * 68 + e] = attr[(size_t)e0 * 32 + i];
    }
    __syncthreads();

    int oc = t & 15, eg = t >> 4;       // eg: edges 4*eg .. 4*eg+3

    // ---- layer 1: 32 -> 64 ----
    {
        float4 b = ((float4*)(sm + OB1))[oc];
        float4 a0 = b, a1 = b, a2 = b, a3 = b;
        #pragma unroll 8
        for (int k = 0; k < 32; k++) {
            float4 wv = *(float4*)(sm + OW1 + k * 64 + 4 * oc);
            float4 x  = *(float4*)(sm + OAT + k * 68 + 4 * eg);
            fma4(a0, x.x, wv); fma4(a1, x.y, wv); fma4(a2, x.z, wv); fma4(a3, x.w, wv);
        }
        a0.x = silu_f(a0.x); a0.y = silu_f(a0.y); a0.z = silu_f(a0.z); a0.w = silu_f(a0.w);
        a1.x = silu_f(a1.x); a1.y = silu_f(a1.y); a1.z = silu_f(a1.z); a1.w = silu_f(a1.w);
        a2.x = silu_f(a2.x); a2.y = silu_f(a2.y); a2.z = silu_f(a2.z); a2.w = silu_f(a2.w);
        a3.x = silu_f(a3.x); a3.y = silu_f(a3.y); a3.z = silu_f(a3.z); a3.w = silu_f(a3.w);
        // store transposed: h1T[out][e]
        *(float4*)(sm + OH1 + (4*oc + 0) * 68 + 4*eg) = make_float4(a0.x, a1.x, a2.x, a3.x);
        *(float4*)(sm + OH1 + (4*oc + 1) * 68 + 4*eg) = make_float4(a0.y, a1.y, a2.y, a3.y);
        *(float4*)(sm + OH1 + (4*oc + 2) * 68 + 4*eg) = make_float4(a0.z, a1.z, a2.z, a3.z);
        *(float4*)(sm + OH1 + (4*oc + 3) * 68 + 4*eg) = make_float4(a0.w, a1.w, a2.w, a3.w);
    }
    __syncthreads();

    // ---- layer 2: 64 -> 128 ----
    {
        float4 bA = ((float4*)(sm + OB2))[oc];
        float4 bB = ((float4*)(sm + OB2))[oc + 16];
        float4 accA[4] = {bA, bA, bA, bA};
        float4 accB[4] = {bB, bB, bB, bB};
        #pragma unroll 8
        for (int k = 0; k < 64; k++) {
            float4 x  = *(float4*)(sm + OH1 + k * 68 + 4 * eg);
            float4 u0 = *(float4*)(sm + OW2 + k * 128 + 4 * oc);
            float4 u1 = *(float4*)(sm + OW2 + k * 128 + 64 + 4 * oc);
            fma4(accA[0], x.x, u0); fma4(accA[1], x.y, u0); fma4(accA[2], x.z, u0); fma4(accA[3], x.w, u0);
            fma4(accB[0], x.x, u1); fma4(accB[1], x.y, u1); fma4(accB[2], x.z, u1); fma4(accB[3], x.w, u1);
        }
        // transpose-store with silu: accA[m] holds edge m, outputs {4oc..4oc+3}
        float* h2 = sm + OH2;
        #pragma unroll
        for (int m = 0; m < 4; m++) {
            float4 vA = accA[m], vB = accB[m];
            h2[(4*oc + 0) * 68 + 4*eg + m] = silu_f(vA.x);
            h2[(4*oc + 1) * 68 + 4*eg + m] = silu_f(vA.y);
            h2[(4*oc + 2) * 68 + 4*eg + m] = silu_f(vA.z);
            h2[(4*oc + 3) * 68 + 4*eg + m] = silu_f(vA.w);
            h2[(64 + 4*oc + 0) * 68 + 4*eg + m] = silu_f(vB.x);
            h2[(64 + 4*oc + 1) * 68 + 4*eg + m] = silu_f(vB.y);
            h2[(64 + 4*oc + 2) * 68 + 4*eg + m] = silu_f(vB.z);
            h2[(64 + 4*oc + 3) * 68 + 4*eg + m] = silu_f(vB.w);
        }
    }
    __syncthreads();

    // ---- layer 3: 128 -> 192 ----
    {
        float4 c0 = ((float4*)(sm + OB3))[oc];
        float4 c1 = ((float4*)(sm + OB3))[oc + 16];
        float4 c2 = ((float4*)(sm + OB3))[oc + 32];
        float4 acc[4][3];
        #pragma unroll
        for (int m = 0; m < 4; m++) { acc[m][0] = c0; acc[m][1] = c1; acc[m][2] = c2; }
        #pragma unroll 4
        for (int k = 0; k < 128; k++) {
            float4 x  = *(float4*)(sm + OH2 + k * 68 + 4 * eg);
            float4 u0 = *(float4*)(sm + OW3 + k * 192 + 4 * oc);
            float4 u1 = *(float4*)(sm + OW3 + k * 192 + 64 + 4 * oc);
            float4 u2 = *(float4*)(sm + OW3 + k * 192 + 128 + 4 * oc);
            fma4(acc[0][0], x.x, u0); fma4(acc[0][1], x.x, u1); fma4(acc[0][2], x.x, u2);
            fma4(acc[1][0], x.y, u0); fma4(acc[1][1], x.y, u1); fma4(acc[1][2], x.y, u2);
            fma4(acc[2][0], x.z, u0); fma4(acc[2][1], x.z, u1); fma4(acc[2][2], x.z, u2);
            fma4(acc[3][0], x.w, u0); fma4(acc[3][1], x.w, u1); fma4(acc[3][2], x.w, u2);
        }
        #pragma unroll
        for (int m = 0; m < 4; m++) {
            int ee = e0 + 4 * eg + m;
            float w = __ldg(ew + ee);
            float cw = 0.5f * (__cosf(w * (PI_F / 5.0f)) + 1.0f);
            cw = (w < 5.0f) ? cw : 0.0f;
            float* op = g_a + (size_t)ee * 192;
            #pragma unroll
            for (int p = 0; p < 3; p++) {
                float4 v = acc[m][p];
                v.x = silu_f(v.x) * cw; v.y = silu_f(v.y) * cw;
                v.z = silu_f(v.z) * cw; v.w = silu_f(v.w) * cw;
                *(float4*)(op + p * 64 + 4 * oc) = v;
            }
        }
    }
}

// ---------------------------------------------------------------------------
// K3: message passing. Thread per (edge, channel).
// ---------------------------------------------------------------------------
__global__ __launch_bounds__(256) void k_message(const int* __restrict__ ei) {
    int idx = blockIdx.x * 256 + threadIdx.x;
    int e = idx >> 6, c = idx & 63;
    int src = __ldg(ei + e);
    int dst = __ldg(ei + Ee + e);
    const float* ap = g_a + (size_t)e * 192 + 3 * c;
    float aI = __ldg(ap), aA = __ldg(ap + 1), aS = __ldg(ap + 2);
    const float4* f = (const float4*)(g_feat + ((size_t)dst * 64 + c) * 12);
    float4 f0 = f[0], f1 = f[1];
    float  f8 = ((const float*)f)[8];
    float* b = g_msg + ((size_t)src * 64 + c) * 12;
    red4(b,     aI * f0.x, aA * f0.y, aA * f0.z, aA * f0.w);
    red4(b + 4, aS * f1.x, aS * f1.y, aS * f1.z, aS * f1.w);
    red1(b + 8, aS * f8);
}

// ---------------------------------------------------------------------------
// K4: finalize — 16 nodes/block, Wt[3..5] staged in smem.
// dyn smem: 12288 + 9216 + 9216 = 30720 floats = 120 KB
// ---------------------------------------------------------------------------
__global__ __launch_bounds__(256) void k_finalize(const float* __restrict__ Wt,
                                                  float* __restrict__ out) {
    extern __shared__ float sm[];
    float* sw   = sm;            // Wt[3..5]
    float* sraw = sm + 12288;
    float* sdx  = sm + 21504;
    int t = threadIdx.x;
    int nb = blockIdx.x * 16;

    for (int i = t; i < 3072; i += 256)
        ((float4*)sw)[i] = ((const float4*)(Wt + 3 * 4096))[i];

    #pragma unroll
    for (int it = 0; it < 4; it++) {
        int p = t + it * 256;
        int s = p >> 6, c = p & 63;
        int n = nb + s;
        const float* mp = g_msg + ((size_t)n * 64 + c) * 12;
        const float* fp = g_feat + ((size_t)n * 64 + c) * 12;
        float mc[9], fc[9];
        #pragma unroll
        for (int i = 0; i < 9; i++) { mc[i] = mp[i]; fc[i] = fp[i]; }
        float Mg[9], Y[9];
        reconstruct(Mg, mc);
        reconstruct(Y, fc);
        float M1[9], M2[9], M[9];
        mm3(M1, Mg, Y);
        mm3(M2, Y, Mg);
        float nrm = 0.f;
        #pragma unroll
        for (int i = 0; i < 9; i++) { M[i] = M1[i] + M2[i]; nrm += M[i] * M[i]; }
        float inv = 1.f / (nrm + 1.f);
        float lam = (M[0] + M[4] + M[8]) * (1.f / 3.f);
        float* r = sraw + (s * 9) * 64 + c;
        r[0*64] = lam * inv;
        r[1*64] = 0.5f * (M[1] - M[3]) * inv;
        r[2*64] = 0.5f * (M[2] - M[6]) * inv;
        r[3*64] = 0.5f * (M[5] - M[7]) * inv;
        r[4*64] = (M[0] - lam) * inv;
        r[5*64] = (M[4] - lam) * inv;
        r[6*64] = 0.5f * (M[1] + M[3]) * inv;
        r[7*64] = 0.5f * (M[2] + M[6]) * inv;
        r[8*64] = 0.5f * (M[5] + M[7]) * inv;
    }
    __syncthreads();

    {
        int l = t & 63, g = t >> 6;
        #pragma unroll
        for (int comp = 0; comp < 9; comp++) {
            int sel = (comp == 0) ? 0 : ((comp < 4) ? 1 : 2);
            const float* w = sw + sel * 4096 + l;
            float a0 = 0.f, a1 = 0.f, a2 = 0.f, a3 = 0.f;
            const float* r0 = sraw + ((g*4 + 0) * 9 + comp) * 64;
            const float* r1 = sraw + ((g*4 + 1) * 9 + comp) * 64;
            const float* r2 = sraw + ((g*4 + 2) * 9 + comp) * 64;
            const float* r3 = sraw + ((g*4 + 3) * 9 + comp) * 64;
            #pragma unroll 16
            for (int k = 0; k < 64; k++) {
                float wv = w[k * 64];
                a0 = fmaf(r0[k], wv, a0);
                a1 = fmaf(r1[k], wv, a1);
                a2 = fmaf(r2[k], wv, a2);
                a3 = fmaf(r3[k], wv, a3);
            }
            sdx[((g*4 + 0) * 9 + comp) * 64 + l] = a0;
            sdx[((g*4 + 1) * 9 + comp) * 64 + l] = a1;
            sdx[((g*4 + 2) * 9 + comp) * 64 + l] = a2;
            sdx[((g*4 + 3) * 9 + comp) * 64 + l] = a3;
        }
    }
    __syncthreads();

    #pragma unroll
    for (int it = 0; it < 4; it++) {
        int p = t + it * 256;
        int s = p >> 6, c = p & 63;
        int n = nb + s;
        float dc[9];
        #pragma unroll
        for (int i = 0; i < 9; i++) dc[i] = sdx[(s * 9 + i) * 64 + c];
        float D[9];
        reconstruct(D, dc);
        float DD[9];
        mm3(DD, D, D);
        const float* xn = g_Xn + ((size_t)n * 64 + c) * 9;
        float* op = out + ((size_t)n * 64 + c) * 9;
        #pragma unroll
        for (int i = 0; i < 9; i++) op[i] = xn[i] + D[i] + DD[i];
    }
}

// ---------------------------------------------------------------------------
extern "C" void kernel_launch(void* const* d_in, const int* in_sizes, int n_in,
                              void* d_out, int out_size) {
    const float* X    = (const float*)d_in[0];
    const int*   ei   = (const int*)  d_in[1];
    const float* ew   = (const float*)d_in[2];
    const float* attr = (const float*)d_in[3];
    const float* W1   = (const float*)d_in[4];
    const float* b1   = (const float*)d_in[5];
    const float* W2   = (const float*)d_in[6];
    const float* b2   = (const float*)d_in[7];
    const float* W3   = (const float*)d_in[8];
    const float* b3   = (const float*)d_in[9];
    const float* Wt   = (const float*)d_in[10];
    float* out = (float*)d_out;

    // Idempotent, non-stream API calls — safe during graph capture, no static guard.
    cudaFuncSetAttribute(k_edge_mlp, cudaFuncAttributeMaxDynamicSharedMemorySize,
                         SM_EDGE_TOT * 4);
    cudaFuncSetAttribute(k_nodeprep, cudaFuncAttributeMaxDynamicSharedMemorySize,
                         21504 * 4);
    cudaFuncSetAttribute(k_finalize, cudaFuncAttributeMaxDynamicSharedMemorySize,
                         30720 * 4);

    k_zero_msg<<<(Nn * Cc * 12 + 255) / 256, 256>>>();
    k_nodeprep<<<Nn / 16, 256, 21504 * 4>>>(X, Wt);
    k_edge_mlp<<<Ee / 64, 256, SM_EDGE_TOT * 4>>>(attr, ew, W1, b1, W2, b2, W3, b3);
    k_message<<<(Ee * Cc) / 256, 256>>>(ei);
    k_finalize<<<Nn / 16, 256, 30720 * 4>>>(Wt, out);
}

// round 8
// speedup vs baseline: 2.8639x; 1.1969x over previous
#include <cuda_runtime.h>
#include <cuda_bf16.h>
#include <cstdint>

#define Nn 10000
#define Ee 160000
#define Cc 64
#define PI_F 3.14159265358979f

// Scratch (global __device__ arrays)
__device__ float g_Xn  [Nn * Cc * 9];           // normalized input tensors, [n][c][9]
__device__ float g_feat[Nn * Cc * 12];          // mixed compressed node feats, [n][c][12] (9 used)
__device__ float g_msg [Nn * Cc * 12];          // compressed message accumulators
__device__ float g_a   [(size_t)Ee * 192];      // edge MLP output, [e][192]

// Pre-transposed, padded bf16 hi/lo weights: [out][K+8] halves
__device__ __align__(16) __nv_bfloat16 g_W1h[64 * 40];
__device__ __align__(16) __nv_bfloat16 g_W1l[64 * 40];
__device__ __align__(16) __nv_bfloat16 g_W2h[128 * 72];
__device__ __align__(16) __nv_bfloat16 g_W2l[128 * 72];
__device__ __align__(16) __nv_bfloat16 g_W3h[192 * 136];
__device__ __align__(16) __nv_bfloat16 g_W3l[192 * 136];

__device__ __forceinline__ float silu_f(float x) {
    return x / (1.f + __expf(-x));
}

__device__ __forceinline__ void red4(float* p, float a, float b, float c, float d) {
    asm volatile("red.global.add.v4.f32 [%0], {%1,%2,%3,%4};"
                 :: "l"(p), "f"(a), "f"(b), "f"(c), "f"(d) : "memory");
}
__device__ __forceinline__ void red1(float* p, float a) {
    asm volatile("red.global.add.f32 [%0], %1;" :: "l"(p), "f"(a) : "memory");
}

__device__ __forceinline__ void reconstruct(float F[9], const float c[9]) {
    float lam = c[0], a01 = c[1], a02 = c[2], a12 = c[3];
    float s00 = c[4], s11 = c[5], s01 = c[6], s02 = c[7], s12 = c[8];
    float s22 = -(s00 + s11);
    F[0] = lam + s00;  F[1] =  a01 + s01; F[2] =  a02 + s02;
    F[3] = -a01 + s01; F[4] = lam + s11;  F[5] =  a12 + s12;
    F[6] = -a02 + s02; F[7] = -a12 + s12; F[8] = lam + s22;
}

__device__ __forceinline__ void mm3(float C[9], const float A[9], const float B[9]) {
    #pragma unroll
    for (int i = 0; i < 3; i++)
        #pragma unroll
        for (int j = 0; j < 3; j++) {
            float acc = 0.f;
            #pragma unroll
            for (int k = 0; k < 3; k++) acc += A[i*3+k] * B[k*3+j];
            C[i*3+j] = acc;
        }
}

// mma.m16n8k16 bf16, fp32 accumulate
__device__ __forceinline__ void mma16816(float* c, const uint32_t* a, uint32_t b0, uint32_t b1) {
    asm volatile(
        "mma.sync.aligned.m16n8k16.row.col.f32.bf16.bf16.f32 "
        "{%0,%1,%2,%3},{%4,%5,%6,%7},{%8,%9},{%0,%1,%2,%3};"
        : "+f"(c[0]), "+f"(c[1]), "+f"(c[2]), "+f"(c[3])
        : "r"(a[0]), "r"(a[1]), "r"(a[2]), "r"(a[3]), "r"(b0), "r"(b1));
}

// split (x0,x1) into packed bf16x2 hi and lo residual
__device__ __forceinline__ void split2(float x0, float x1, uint32_t& hi, uint32_t& lo) {
    __nv_bfloat162 h = __floats2bfloat162_rn(x0, x1);
    float r0 = x0 - __bfloat162float(h.x);
    float r1 = x1 - __bfloat162float(h.y);
    __nv_bfloat162 l = __floats2bfloat162_rn(r0, r1);
    hi = *(uint32_t*)&h;
    lo = *(uint32_t*)&l;
}

// ---------------------------------------------------------------------------
// K0: zero message accumulators
// ---------------------------------------------------------------------------
__global__ void k_zero_msg() {
    int i = blockIdx.x * 256 + threadIdx.x;
    if (i < Nn * Cc * 12) g_msg[i] = 0.f;
}

// ---------------------------------------------------------------------------
// KW: weight prep — transpose + pad + bf16 hi/lo split
// W stored [in][out] row-major; output [out][Kpad] halves.
// ---------------------------------------------------------------------------
__global__ void k_wprep(const float* __restrict__ W1, const float* __restrict__ W2,
                        const float* __restrict__ W3) {
    int idx = blockIdx.x * 256 + threadIdx.x;
    float w; __nv_bfloat16* ph; __nv_bfloat16* pl; int off;
    if (idx < 2048) {                 // W1: [32][64]
        int in = idx >> 6, out = idx & 63;
        w = W1[idx]; ph = g_W1h; pl = g_W1l; off = out * 40 + in;
    } else if (idx < 2048 + 8192) {   // W2: [64][128]
        int j = idx - 2048;
        int in = j >> 7, out = j & 127;
        w = W2[j]; ph = g_W2h; pl = g_W2l; off = out * 72 + in;
    } else if (idx < 2048 + 8192 + 24576) {  // W3: [128][192]
        int j = idx - 10240;
        int in = j / 192, out = j % 192;
        w = W3[j]; ph = g_W3h; pl = g_W3l; off = out * 136 + in;
    } else return;
    __nv_bfloat16 h = __float2bfloat16_rn(w);
    ph[off] = h;
    pl[off] = __float2bfloat16_rn(w - __bfloat162float(h));
}

// ---------------------------------------------------------------------------
// K1: node prep — 16 nodes/block, Wt[0..2] staged in smem.
// ---------------------------------------------------------------------------
__global__ __launch_bounds__(256) void k_nodeprep(const float* __restrict__ X,
                                                  const float* __restrict__ Wt) {
    extern __shared__ float sm[];
    float* sw   = sm;            // 3 * 4096
    float* sraw = sm + 12288;    // [16 nodes][9 comps][64 ch]
    int t = threadIdx.x;
    int nb = blockIdx.x * 16;

    for (int i = t; i < 3072; i += 256)
        ((float4*)sw)[i] = ((const float4*)Wt)[i];

    #pragma unroll
    for (int it = 0; it < 4; it++) {
        int p = t + it * 256;
        int s = p >> 6, c = p & 63;
        int n = nb + s;
        const float* xp = X + (size_t)(n * 64 + c) * 9;
        float x[9]; float n2 = 0.f;
        #pragma unroll
        for (int i = 0; i < 9; i++) { x[i] = xp[i]; n2 += x[i] * x[i]; }
        float inv = 1.f / (n2 + 1.f);
        float* xo = g_Xn + (size_t)(n * 64 + c) * 9;
        #pragma unroll
        for (int i = 0; i < 9; i++) { x[i] *= inv; xo[i] = x[i]; }
        float lam = (x[0] + x[4] + x[8]) * (1.f / 3.f);
        float* r = sraw + (s * 9) * 64 + c;
        r[0*64] = lam;
        r[1*64] = 0.5f * (x[1] - x[3]);
        r[2*64] = 0.5f * (x[2] - x[6]);
        r[3*64] = 0.5f * (x[5] - x[7]);
        r[4*64] = x[0] - lam;
        r[5*64] = x[4] - lam;
        r[6*64] = 0.5f * (x[1] + x[3]);
        r[7*64] = 0.5f * (x[2] + x[6]);
        r[8*64] = 0.5f * (x[5] + x[7]);
    }
    __syncthreads();

    int l = t & 63, g = t >> 6;           // g: 4 nodes each
    #pragma unroll
    for (int comp = 0; comp < 9; comp++) {
        int sel = (comp == 0) ? 0 : ((comp < 4) ? 1 : 2);
        const float* w = sw + sel * 4096 + l;
        float a0 = 0.f, a1 = 0.f, a2 = 0.f, a3 = 0.f;
        const float* r0 = sraw + ((g*4 + 0) * 9 + comp) * 64;
        const float* r1 = sraw + ((g*4 + 1) * 9 + comp) * 64;
        const float* r2 = sraw + ((g*4 + 2) * 9 + comp) * 64;
        const float* r3 = sraw + ((g*4 + 3) * 9 + comp) * 64;
        #pragma unroll 16
        for (int k = 0; k < 64; k++) {
            float wv = w[k * 64];
            a0 = fmaf(r0[k], wv, a0);
            a1 = fmaf(r1[k], wv, a1);
            a2 = fmaf(r2[k], wv, a2);
            a3 = fmaf(r3[k], wv, a3);
        }
        int n0 = nb + g * 4;
        g_feat[((size_t)(n0+0) * 64 + l) * 12 + comp] = a0;
        g_feat[((size_t)(n0+1) * 64 + l) * 12 + comp] = a1;
        g_feat[((size_t)(n0+2) * 64 + l) * 12 + comp] = a2;
        g_feat[((size_t)(n0+3) * 64 + l) * 12 + comp] = a3;
    }
}

// ---------------------------------------------------------------------------
// K2: edge MLP via mma.sync bf16 double-split (hi/lo, 3 mmas per product).
// 64 edges/block, 256 threads = 8 warps = 4 m-tiles x 2 n-halves.
// ---------------------------------------------------------------------------
#define EOFF_W1H 0
#define EOFF_W1L 5120
#define EOFF_W2H 10240
#define EOFF_W2L 28672
#define EOFF_W3H 47104
#define EOFF_W3L 99328
#define EOFF_A1H 151552
#define EOFF_A1L 156672
#define EOFF_A2H 161792
#define EOFF_A2L 171008
#define EOFF_A3H 180224
#define EOFF_A3L 197632
#define EOFF_B   215040
#define EDGE_SMEM_BYTES 216576

__global__ __launch_bounds__(256) void k_edge_mlp_mma(
    const float* __restrict__ attr, const float* __restrict__ ew,
    const float* __restrict__ b1, const float* __restrict__ b2,
    const float* __restrict__ b3) {
    extern __shared__ __align__(16) uint8_t smraw[];
    uint32_t* W1h = (uint32_t*)(smraw + EOFF_W1H);
    uint32_t* W1l = (uint32_t*)(smraw + EOFF_W1L);
    uint32_t* W2h = (uint32_t*)(smraw + EOFF_W2H);
    uint32_t* W2l = (uint32_t*)(smraw + EOFF_W2L);
    uint32_t* W3h = (uint32_t*)(smraw + EOFF_W3H);
    uint32_t* W3l = (uint32_t*)(smraw + EOFF_W3L);
    uint32_t* A1h = (uint32_t*)(smraw + EOFF_A1H);
    uint32_t* A1l = (uint32_t*)(smraw + EOFF_A1L);
    uint32_t* A2h = (uint32_t*)(smraw + EOFF_A2H);
    uint32_t* A2l = (uint32_t*)(smraw + EOFF_A2L);
    uint32_t* A3h = (uint32_t*)(smraw + EOFF_A3H);
    uint32_t* A3l = (uint32_t*)(smraw + EOFF_A3L);
    float*    sB  = (float*)(smraw + EOFF_B);

    int t = threadIdx.x;
    int e0 = blockIdx.x * 64;

    // ---- stage weights (uint4 copies) ----
    for (int i = t; i < 320;  i += 256) ((uint4*)(smraw + EOFF_W1H))[i] = ((const uint4*)g_W1h)[i];
    for (int i = t; i < 320;  i += 256) ((uint4*)(smraw + EOFF_W1L))[i] = ((const uint4*)g_W1l)[i];
    for (int i = t; i < 1152; i += 256) ((uint4*)(smraw + EOFF_W2H))[i] = ((const uint4*)g_W2h)[i];
    for (int i = t; i < 1152; i += 256) ((uint4*)(smraw + EOFF_W2L))[i] = ((const uint4*)g_W2l)[i];
    for (int i = t; i < 3264; i += 256) ((uint4*)(smraw + EOFF_W3H))[i] = ((const uint4*)g_W3h)[i];
    for (int i = t; i < 3264; i += 256) ((uint4*)(smraw + EOFF_W3L))[i] = ((const uint4*)g_W3l)[i];
    for (int i = t; i < 384;  i += 256)
        sB[i] = (i < 64) ? b1[i] : (i < 192) ? b2[i - 64] : b3[i - 192];

    // ---- stage attr -> A1 hi/lo bf16 (pairs) ----
    #pragma unroll
    for (int i = 0; i < 4; i++) {
        int p = t + i * 256;          // pair index 0..1023
        int e = p >> 4, kp = p & 15;
        float2 x = *(const float2*)(attr + (size_t)(e0 + e) * 32 + kp * 2);
        uint32_t h, l;
        split2(x.x, x.y, h, l);
        A1h[e * 20 + kp] = h;
        A1l[e * 20 + kp] = l;
    }
    __syncthreads();

    int lane = t & 31, wid = t >> 5;
    int g = lane >> 2, tg = lane & 3;
    int m0 = (wid & 3) * 16;          // 4 m-tiles of 16 edges
    int nh = wid >> 2;                // n-half 0/1

    // ================= layer 1: K=32 -> N=64 =================
    {
        int n0base = nh * 32;         // 4 n-tiles
        float acc[4][4] = {};
        #pragma unroll
        for (int kt = 0; kt < 2; kt++) {
            uint32_t ah[4], al[4];
            int ab = (m0 + g) * 20 + kt * 8 + tg;
            ah[0] = A1h[ab]; ah[1] = A1h[ab + 160]; ah[2] = A1h[ab + 4]; ah[3] = A1h[ab + 164];
            al[0] = A1l[ab]; al[1] = A1l[ab + 160]; al[2] = A1l[ab + 4]; al[3] = A1l[ab + 164];
            #pragma unroll
            for (int nt = 0; nt < 4; nt++) {
                int bb = (n0base + nt * 8 + g) * 20 + kt * 8 + tg;
                uint32_t b0h = W1h[bb], b1h = W1h[bb + 4];
                uint32_t b0l = W1l[bb], b1l = W1l[bb + 4];
                mma16816(acc[nt], ah, b0h, b1h);
                mma16816(acc[nt], ah, b0l, b1l);
                mma16816(acc[nt], al, b0h, b1h);
            }
        }
        #pragma unroll
        for (int nt = 0; nt < 4; nt++) {
            int col = n0base + nt * 8 + 2 * tg;
            float bb0 = sB[col], bb1 = sB[col + 1];
            uint32_t h, l;
            split2(silu_f(acc[nt][0] + bb0), silu_f(acc[nt][1] + bb1), h, l);
            A2h[(m0 + g) * 36 + (col >> 1)] = h;
            A2l[(m0 + g) * 36 + (col >> 1)] = l;
            split2(silu_f(acc[nt][2] + bb0), silu_f(acc[nt][3] + bb1), h, l);
            A2h[(m0 + g + 8) * 36 + (col >> 1)] = h;
            A2l[(m0 + g + 8) * 36 + (col >> 1)] = l;
        }
    }
    __syncthreads();

    // ================= layer 2: K=64 -> N=128 =================
    {
        int n0base = nh * 64;         // 8 n-tiles
        float acc[8][4] = {};
        #pragma unroll
        for (int kt = 0; kt < 4; kt++) {
            uint32_t ah[4], al[4];
            int ab = (m0 + g) * 36 + kt * 8 + tg;
            ah[0] = A2h[ab]; ah[1] = A2h[ab + 288]; ah[2] = A2h[ab + 4]; ah[3] = A2h[ab + 292];
            al[0] = A2l[ab]; al[1] = A2l[ab + 288]; al[2] = A2l[ab + 4]; al[3] = A2l[ab + 292];
            #pragma unroll
            for (int nt = 0; nt < 8; nt++) {
                int bb = (n0base + nt * 8 + g) * 36 + kt * 8 + tg;
                uint32_t b0h = W2h[bb], b1h = W2h[bb + 4];
                uint32_t b0l = W2l[bb], b1l = W2l[bb + 4];
                mma16816(acc[nt], ah, b0h, b1h);
                mma16816(acc[nt], ah, b0l, b1l);
                mma16816(acc[nt], al, b0h, b1h);
            }
        }
        #pragma unroll
        for (int nt = 0; nt < 8; nt++) {
            int col = n0base + nt * 8 + 2 * tg;
            float bb0 = sB[64 + col], bb1 = sB[64 + col + 1];
            uint32_t h, l;
            split2(silu_f(acc[nt][0] + bb0), silu_f(acc[nt][1] + bb1), h, l);
            A3h[(m0 + g) * 68 + (col >> 1)] = h;
            A3l[(m0 + g) * 68 + (col >> 1)] = l;
            split2(silu_f(acc[nt][2] + bb0), silu_f(acc[nt][3] + bb1), h, l);
            A3h[(m0 + g + 8) * 68 + (col >> 1)] = h;
            A3l[(m0 + g + 8) * 68 + (col >> 1)] = l;
        }
    }
    __syncthreads();

    // ================= layer 3: K=128 -> N=192 =================
    {
        int n0base = nh * 96;         // 12 n-tiles
        float acc[12][4] = {};
        #pragma unroll
        for (int kt = 0; kt < 8; kt++) {
            uint32_t ah[4], al[4];
            int ab = (m0 + g) * 68 + kt * 8 + tg;
            ah[0] = A3h[ab]; ah[1] = A3h[ab + 544]; ah[2] = A3h[ab + 4]; ah[3] = A3h[ab + 548];
            al[0] = A3l[ab]; al[1] = A3l[ab + 544]; al[2] = A3l[ab + 4]; al[3] = A3l[ab + 548];
            #pragma unroll
            for (int nt = 0; nt < 12; nt++) {
                int bb = (n0base + nt * 8 + g) * 68 + kt * 8 + tg;
                uint32_t b0h = W3h[bb], b1h = W3h[bb + 4];
                uint32_t b0l = W3l[bb], b1l = W3l[bb + 4];
                mma16816(acc[nt], ah, b0h, b1h);
                mma16816(acc[nt], ah, b0l, b1l);
                mma16816(acc[nt], al, b0h, b1h);
            }
        }
        // cutoff per edge rows m0+g, m0+g+8
        float w0 = ew[e0 + m0 + g];
        float w1 = ew[e0 + m0 + g + 8];
        float cw0 = 0.5f * (__cosf(w0 * (PI_F / 5.0f)) + 1.0f); cw0 = (w0 < 5.0f) ? cw0 : 0.0f;
        float cw1 = 0.5f * (__cosf(w1 * (PI_F / 5.0f)) + 1.0f); cw1 = (w1 < 5.0f) ? cw1 : 0.0f;
        float* o0 = g_a + (size_t)(e0 + m0 + g) * 192;
        float* o1 = g_a + (size_t)(e0 + m0 + g + 8) * 192;
        #pragma unroll
        for (int nt = 0; nt < 12; nt++) {
            int col = n0base + nt * 8 + 2 * tg;
            float bb0 = sB[192 + col], bb1 = sB[192 + col + 1];
            float2 v0 = make_float2(silu_f(acc[nt][0] + bb0) * cw0,
                                    silu_f(acc[nt][1] + bb1) * cw0);
            float2 v1 = make_float2(silu_f(acc[nt][2] + bb0) * cw1,
                                    silu_f(acc[nt][3] + bb1) * cw1);
            *(float2*)(o0 + col) = v0;
            *(float2*)(o1 + col) = v1;
        }
    }
}

// ---------------------------------------------------------------------------
// K3: message passing. Thread per (edge, channel).
// ---------------------------------------------------------------------------
__global__ __launch_bounds__(256) void k_message(const int* __restrict__ ei) {
    int idx = blockIdx.x * 256 + threadIdx.x;
    int e = idx >> 6, c = idx & 63;
    int src = __ldg(ei + e);
    int dst = __ldg(ei + Ee + e);
    const float* ap = g_a + (size_t)e * 192 + 3 * c;
    float aI = __ldg(ap), aA = __ldg(ap + 1), aS = __ldg(ap + 2);
    const float4* f = (const float4*)(g_feat + ((size_t)dst * 64 + c) * 12);
    float4 f0 = f[0], f1 = f[1];
    float  f8 = ((const float*)f)[8];
    float* b = g_msg + ((size_t)src * 64 + c) * 12;
    red4(b,     aI * f0.x, aA * f0.y, aA * f0.z, aA * f0.w);
    red4(b + 4, aS * f1.x, aS * f1.y, aS * f1.z, aS * f1.w);
    red1(b + 8, aS * f8);
}

// ---------------------------------------------------------------------------
// K4: finalize — 16 nodes/block, Wt[3..5] staged in smem.
// ---------------------------------------------------------------------------
__global__ __launch_bounds__(256) void k_finalize(const float* __restrict__ Wt,
                                                  float* __restrict__ out) {
    extern __shared__ float sm[];
    float* sw   = sm;            // Wt[3..5]
    float* sraw = sm + 12288;
    float* sdx  = sm + 21504;
    int t = threadIdx.x;
    int nb = blockIdx.x * 16;

    for (int i = t; i < 3072; i += 256)
        ((float4*)sw)[i] = ((const float4*)(Wt + 3 * 4096))[i];

    #pragma unroll
    for (int it = 0; it < 4; it++) {
        int p = t + it * 256;
        int s = p >> 6, c = p & 63;
        int n = nb + s;
        const float* mp = g_msg + ((size_t)n * 64 + c) * 12;
        const float* fp = g_feat + ((size_t)n * 64 + c) * 12;
        float mc[9], fc[9];
        #pragma unroll
        for (int i = 0; i < 9; i++) { mc[i] = mp[i]; fc[i] = fp[i]; }
        float Mg[9], Y[9];
        reconstruct(Mg, mc);
        reconstruct(Y, fc);
        float M1[9], M2[9], M[9];
        mm3(M1, Mg, Y);
        mm3(M2, Y, Mg);
        float nrm = 0.f;
        #pragma unroll
        for (int i = 0; i < 9; i++) { M[i] = M1[i] + M2[i]; nrm += M[i] * M[i]; }
        float inv = 1.f / (nrm + 1.f);
        float lam = (M[0] + M[4] + M[8]) * (1.f / 3.f);
        float* r = sraw + (s * 9) * 64 + c;
        r[0*64] = lam * inv;
        r[1*64] = 0.5f * (M[1] - M[3]) * inv;
        r[2*64] = 0.5f * (M[2] - M[6]) * inv;
        r[3*64] = 0.5f * (M[5] - M[7]) * inv;
        r[4*64] = (M[0] - lam) * inv;
        r[5*64] = (M[4] - lam) * inv;
        r[6*64] = 0.5f * (M[1] + M[3]) * inv;
        r[7*64] = 0.5f * (M[2] + M[6]) * inv;
        r[8*64] = 0.5f * (M[5] + M[7]) * inv;
    }
    __syncthreads();

    {
        int l = t & 63, g = t >> 6;
        #pragma unroll
        for (int comp = 0; comp < 9; comp++) {
            int sel = (comp == 0) ? 0 : ((comp < 4) ? 1 : 2);
            const float* w = sw + sel * 4096 + l;
            float a0 = 0.f, a1 = 0.f, a2 = 0.f, a3 = 0.f;
            const float* r0 = sraw + ((g*4 + 0) * 9 + comp) * 64;
            const float* r1 = sraw + ((g*4 + 1) * 9 + comp) * 64;
            const float* r2 = sraw + ((g*4 + 2) * 9 + comp) * 64;
            const float* r3 = sraw + ((g*4 + 3) * 9 + comp) * 64;
            #pragma unroll 16
            for (int k = 0; k < 64; k++) {
                float wv = w[k * 64];
                a0 = fmaf(r0[k], wv, a0);
                a1 = fmaf(r1[k], wv, a1);
                a2 = fmaf(r2[k], wv, a2);
                a3 = fmaf(r3[k], wv, a3);
            }
            sdx[((g*4 + 0) * 9 + comp) * 64 + l] = a0;
            sdx[((g*4 + 1) * 9 + comp) * 64 + l] = a1;
            sdx[((g*4 + 2) * 9 + comp) * 64 + l] = a2;
            sdx[((g*4 + 3) * 9 + comp) * 64 + l] = a3;
        }
    }
    __syncthreads();

    #pragma unroll
    for (int it = 0; it < 4; it++) {
        int p = t + it * 256;
        int s = p >> 6, c = p & 63;
        int n = nb + s;
        float dc[9];
        #pragma unroll
        for (int i = 0; i < 9; i++) dc[i] = sdx[(s * 9 + i) * 64 + c];
        float D[9];
        reconstruct(D, dc);
        float DD[9];
        mm3(DD, D, D);
        const float* xn = g_Xn + ((size_t)n * 64 + c) * 9;
        float* op = out + ((size_t)n * 64 + c) * 9;
        #pragma unroll
        for (int i = 0; i < 9; i++) op[i] = xn[i] + D[i] + DD[i];
    }
}

// ---------------------------------------------------------------------------
extern "C" void kernel_launch(void* const* d_in, const int* in_sizes, int n_in,
                              void* d_out, int out_size) {
    const float* X    = (const float*)d_in[0];
    const int*   ei   = (const int*)  d_in[1];
    const float* ew   = (const float*)d_in[2];
    const float* attr = (const float*)d_in[3];
    const float* W1   = (const float*)d_in[4];
    const float* b1   = (const float*)d_in[5];
    const float* W2   = (const float*)d_in[6];
    const float* b2   = (const float*)d_in[7];
    const float* W3   = (const float*)d_in[8];
    const float* b3   = (const float*)d_in[9];
    const float* Wt   = (const float*)d_in[10];
    float* out = (float*)d_out;

    // Idempotent, non-stream API calls — safe during graph capture, no static guard.
    cudaFuncSetAttribute(k_edge_mlp_mma, cudaFuncAttributeMaxDynamicSharedMemorySize,
                         EDGE_SMEM_BYTES);
    cudaFuncSetAttribute(k_nodeprep, cudaFuncAttributeMaxDynamicSharedMemorySize,
                         21504 * 4);
    cudaFuncSetAttribute(k_finalize, cudaFuncAttributeMaxDynamicSharedMemorySize,
                         30720 * 4);

    k_zero_msg<<<(Nn * Cc * 12 + 255) / 256, 256>>>();
    k_wprep<<<(34816 + 255) / 256, 256>>>(W1, W2, W3);
    k_nodeprep<<<Nn / 16, 256, 21504 * 4>>>(X, Wt);
    k_edge_mlp_mma<<<Ee / 64, 256, EDGE_SMEM_BYTES>>>(attr, ew, b1, b2, b3);
    k_message<<<(Ee * Cc) / 256, 256>>>(ei);
    k_finalize<<<Nn / 16, 256, 30720 * 4>>>(Wt, out);
}

// round 11
// speedup vs baseline: 3.7533x; 1.3106x over previous
#include <cuda_runtime.h>
#include <cuda_bf16.h>
#include <cstdint>

#define Nn 10000
#define Ee 160000
#define Cc 64
#define PI_F 3.14159265358979f
#define NTILES 2500

// Scratch (global __device__ arrays)
__device__ float g_Xn  [Nn * Cc * 9];
__device__ float g_feat[Nn * Cc * 12];
__device__ float g_msg [Nn * Cc * 12];
__device__ float g_a   [(size_t)Ee * 192];

// Pre-transposed, padded bf16 hi/lo weights: [out][K+8] halves
__device__ __align__(16) __nv_bfloat16 g_W1h[64 * 40];
__device__ __align__(16) __nv_bfloat16 g_W1l[64 * 40];
__device__ __align__(16) __nv_bfloat16 g_W2h[128 * 72];
__device__ __align__(16) __nv_bfloat16 g_W2l[128 * 72];
__device__ __align__(16) __nv_bfloat16 g_W3h[192 * 136];
__device__ __align__(16) __nv_bfloat16 g_W3l[192 * 136];

__device__ __forceinline__ float silu_f(float x) {
    return x / (1.f + __expf(-x));
}

__device__ __forceinline__ void red4(float* p, float a, float b, float c, float d) {
    asm volatile("red.global.add.v4.f32 [%0], {%1,%2,%3,%4};"
                 :: "l"(p), "f"(a), "f"(b), "f"(c), "f"(d) : "memory");
}
__device__ __forceinline__ void red1(float* p, float a) {
    asm volatile("red.global.add.f32 [%0], %1;" :: "l"(p), "f"(a) : "memory");
}

__device__ __forceinline__ void reconstruct(float F[9], const float c[9]) {
    float lam = c[0], a01 = c[1], a02 = c[2], a12 = c[3];
    float s00 = c[4], s11 = c[5], s01 = c[6], s02 = c[7], s12 = c[8];
    float s22 = -(s00 + s11);
    F[0] = lam + s00;  F[1] =  a01 + s01; F[2] =  a02 + s02;
    F[3] = -a01 + s01; F[4] = lam + s11;  F[5] =  a12 + s12;
    F[6] = -a02 + s02; F[7] = -a12 + s12; F[8] = lam + s22;
}

__device__ __forceinline__ void mm3(float C[9], const float A[9], const float B[9]) {
    #pragma unroll
    for (int i = 0; i < 3; i++)
        #pragma unroll
        for (int j = 0; j < 3; j++) {
            float acc = 0.f;
            #pragma unroll
            for (int k = 0; k < 3; k++) acc += A[i*3+k] * B[k*3+j];
            C[i*3+j] = acc;
        }
}

// mma.m16n8k16 bf16, fp32 accumulate
__device__ __forceinline__ void mma16816(float* c, const uint32_t* a, uint32_t b0, uint32_t b1) {
    asm volatile(
        "mma.sync.aligned.m16n8k16.row.col.f32.bf16.bf16.f32 "
        "{%0,%1,%2,%3},{%4,%5,%6,%7},{%8,%9},{%0,%1,%2,%3};"
        : "+f"(c[0]), "+f"(c[1]), "+f"(c[2]), "+f"(c[3])
        : "r"(a[0]), "r"(a[1]), "r"(a[2]), "r"(a[3]), "r"(b0), "r"(b1));
}

// split (x0,x1) into packed bf16x2 hi and lo residual
__device__ __forceinline__ void split2(float x0, float x1, uint32_t& hi, uint32_t& lo) {
    __nv_bfloat162 h = __floats2bfloat162_rn(x0, x1);
    float r0 = x0 - __bfloat162float(h.x);
    float r1 = x1 - __bfloat162float(h.y);
    __nv_bfloat162 l = __floats2bfloat162_rn(r0, r1);
    hi = *(uint32_t*)&h;
    lo = *(uint32_t*)&l;
}

// ---------------------------------------------------------------------------
// K0: zero message accumulators
// ---------------------------------------------------------------------------
__global__ void k_zero_msg() {
    int i = blockIdx.x * 256 + threadIdx.x;
    if (i < Nn * Cc * 12) g_msg[i] = 0.f;
}

// ---------------------------------------------------------------------------
// KW: weight prep — transpose + pad + bf16 hi/lo split
// ---------------------------------------------------------------------------
__global__ void k_wprep(const float* __restrict__ W1, const float* __restrict__ W2,
                        const float* __restrict__ W3) {
    int idx = blockIdx.x * 256 + threadIdx.x;
    float w; __nv_bfloat16* ph; __nv_bfloat16* pl; int off;
    if (idx < 2048) {                 // W1: [32][64]
        int in = idx >> 6, out = idx & 63;
        w = W1[idx]; ph = g_W1h; pl = g_W1l; off = out * 40 + in;
    } else if (idx < 2048 + 8192) {   // W2: [64][128]
        int j = idx - 2048;
        int in = j >> 7, out = j & 127;
        w = W2[j]; ph = g_W2h; pl = g_W2l; off = out * 72 + in;
    } else if (idx < 2048 + 8192 + 24576) {  // W3: [128][192]
        int j = idx - 10240;
        int in = j / 192, out = j % 192;
        w = W3[j]; ph = g_W3h; pl = g_W3l; off = out * 136 + in;
    } else return;
    __nv_bfloat16 h = __float2bfloat16_rn(w);
    ph[off] = h;
    pl[off] = __float2bfloat16_rn(w - __bfloat162float(h));
}

// ---------------------------------------------------------------------------
// K1: node prep — 16 nodes/block, Wt[0..2] staged in smem.
// ---------------------------------------------------------------------------
__global__ __launch_bounds__(256) void k_nodeprep(const float* __restrict__ X,
                                                  const float* __restrict__ Wt) {
    extern __shared__ float sm[];
    float* sw   = sm;            // 3 * 4096
    float* sraw = sm + 12288;    // [16 nodes][9 comps][64 ch]
    int t = threadIdx.x;
    int nb = blockIdx.x * 16;

    for (int i = t; i < 3072; i += 256)
        ((float4*)sw)[i] = ((const float4*)Wt)[i];

    #pragma unroll
    for (int it = 0; it < 4; it++) {
        int p = t + it * 256;
        int s = p >> 6, c = p & 63;
        int n = nb + s;
        const float* xp = X + (size_t)(n * 64 + c) * 9;
        float x[9]; float n2 = 0.f;
        #pragma unroll
        for (int i = 0; i < 9; i++) { x[i] = xp[i]; n2 += x[i] * x[i]; }
        float inv = 1.f / (n2 + 1.f);
        float* xo = g_Xn + (size_t)(n * 64 + c) * 9;
        #pragma unroll
        for (int i = 0; i < 9; i++) { x[i] *= inv; xo[i] = x[i]; }
        float lam = (x[0] + x[4] + x[8]) * (1.f / 3.f);
        float* r = sraw + (s * 9) * 64 + c;
        r[0*64] = lam;
        r[1*64] = 0.5f * (x[1] - x[3]);
        r[2*64] = 0.5f * (x[2] - x[6]);
        r[3*64] = 0.5f * (x[5] - x[7]);
        r[4*64] = x[0] - lam;
        r[5*64] = x[4] - lam;
        r[6*64] = 0.5f * (x[1] + x[3]);
        r[7*64] = 0.5f * (x[2] + x[6]);
        r[8*64] = 0.5f * (x[5] + x[7]);
    }
    __syncthreads();

    int l = t & 63, g = t >> 6;           // g: 4 nodes each
    #pragma unroll
    for (int comp = 0; comp < 9; comp++) {
        int sel = (comp == 0) ? 0 : ((comp < 4) ? 1 : 2);
        const float* w = sw + sel * 4096 + l;
        float a0 = 0.f, a1 = 0.f, a2 = 0.f, a3 = 0.f;
        const float* r0 = sraw + ((g*4 + 0) * 9 + comp) * 64;
        const float* r1 = sraw + ((g*4 + 1) * 9 + comp) * 64;
        const float* r2 = sraw + ((g*4 + 2) * 9 + comp) * 64;
        const float* r3 = sraw + ((g*4 + 3) * 9 + comp) * 64;
        #pragma unroll 16
        for (int k = 0; k < 64; k++) {
            float wv = w[k * 64];
            a0 = fmaf(r0[k], wv, a0);
            a1 = fmaf(r1[k], wv, a1);
            a2 = fmaf(r2[k], wv, a2);
            a3 = fmaf(r3[k], wv, a3);
        }
        int n0 = nb + g * 4;
        g_feat[((size_t)(n0+0) * 64 + l) * 12 + comp] = a0;
        g_feat[((size_t)(n0+1) * 64 + l) * 12 + comp] = a1;
        g_feat[((size_t)(n0+2) * 64 + l) * 12 + comp] = a2;
        g_feat[((size_t)(n0+3) * 64 + l) * 12 + comp] = a3;
    }
}

// ---------------------------------------------------------------------------
// K2: edge MLP via mma.sync bf16 double-split, persistent blocks.
// grid=148, 512 threads = 16 warps = 4 m-tiles x 4 n-quarters.
// Each block loops over 64-edge tiles (stride gridDim); weights staged ONCE.
// ---------------------------------------------------------------------------
#define EOFF_W1H 0
#define EOFF_W1L 5120
#define EOFF_W2H 10240
#define EOFF_W2L 28672
#define EOFF_W3H 47104
#define EOFF_W3L 99328
#define EOFF_A1H 151552
#define EOFF_A1L 156672
#define EOFF_A2H 161792
#define EOFF_A2L 171008
#define EOFF_A3H 180224
#define EOFF_A3L 197632
#define EOFF_B   215040
#define EDGE_SMEM_BYTES 216576

__global__ __launch_bounds__(512) void k_edge_mlp_mma(
    const float* __restrict__ attr, const float* __restrict__ ew,
    const float* __restrict__ b1, const float* __restrict__ b2,
    const float* __restrict__ b3) {
    extern __shared__ __align__(16) uint8_t smraw[];
    uint32_t* W1h = (uint32_t*)(smraw + EOFF_W1H);
    uint32_t* W1l = (uint32_t*)(smraw + EOFF_W1L);
    uint32_t* W2h = (uint32_t*)(smraw + EOFF_W2H);
    uint32_t* W2l = (uint32_t*)(smraw + EOFF_W2L);
    uint32_t* W3h = (uint32_t*)(smraw + EOFF_W3H);
    uint32_t* W3l = (uint32_t*)(smraw + EOFF_W3L);
    uint32_t* A1h = (uint32_t*)(smraw + EOFF_A1H);
    uint32_t* A1l = (uint32_t*)(smraw + EOFF_A1L);
    uint32_t* A2h = (uint32_t*)(smraw + EOFF_A2H);
    uint32_t* A2l = (uint32_t*)(smraw + EOFF_A2L);
    uint32_t* A3h = (uint32_t*)(smraw + EOFF_A3H);
    uint32_t* A3l = (uint32_t*)(smraw + EOFF_A3L);
    float*    sB  = (float*)(smraw + EOFF_B);

    int t = threadIdx.x;

    // ---- stage ALL weights once per block (persistent) ----
    for (int i = t; i < 320;  i += 512) ((uint4*)(smraw + EOFF_W1H))[i] = ((const uint4*)g_W1h)[i];
    for (int i = t; i < 320;  i += 512) ((uint4*)(smraw + EOFF_W1L))[i] = ((const uint4*)g_W1l)[i];
    for (int i = t; i < 1152; i += 512) ((uint4*)(smraw + EOFF_W2H))[i] = ((const uint4*)g_W2h)[i];
    for (int i = t; i < 1152; i += 512) ((uint4*)(smraw + EOFF_W2L))[i] = ((const uint4*)g_W2l)[i];
    for (int i = t; i < 3264; i += 512) ((uint4*)(smraw + EOFF_W3H))[i] = ((const uint4*)g_W3h)[i];
    for (int i = t; i < 3264; i += 512) ((uint4*)(smraw + EOFF_W3L))[i] = ((const uint4*)g_W3l)[i];
    for (int i = t; i < 384;  i += 512)
        sB[i] = (i < 64) ? b1[i] : (i < 192) ? b2[i - 64] : b3[i - 192];

    int lane = t & 31, wid = t >> 5;
    int g = lane >> 2, tg = lane & 3;
    int m0 = (wid & 3) * 16;          // 4 m-tiles of 16 edges
    int nq = wid >> 2;                // n-quarter 0..3

    for (int tidx = blockIdx.x; tidx < NTILES; tidx += gridDim.x) {
        int e0 = tidx * 64;

        // ---- stage attr -> A1 hi/lo bf16 (1024 pairs) ----
        #pragma unroll
        for (int i = 0; i < 2; i++) {
            int p = t + i * 512;
            int e = p >> 4, kp = p & 15;
            float2 x = *(const float2*)(attr + (size_t)(e0 + e) * 32 + kp * 2);
            uint32_t h, l;
            split2(x.x, x.y, h, l);
            A1h[e * 20 + kp] = h;
            A1l[e * 20 + kp] = l;
        }
        __syncthreads();

        // ================= layer 1: K=32 -> N=64, 2 n-tiles/warp =============
        {
            int n0base = nq * 16;
            float acc[2][4] = {};
            #pragma unroll
            for (int kt = 0; kt < 2; kt++) {
                uint32_t ah[4], al[4];
                int ab = (m0 + g) * 20 + kt * 8 + tg;
                ah[0] = A1h[ab]; ah[1] = A1h[ab + 160]; ah[2] = A1h[ab + 4]; ah[3] = A1h[ab + 164];
                al[0] = A1l[ab]; al[1] = A1l[ab + 160]; al[2] = A1l[ab + 4]; al[3] = A1l[ab + 164];
                #pragma unroll
                for (int nt = 0; nt < 2; nt++) {
                    int bb = (n0base + nt * 8 + g) * 20 + kt * 8 + tg;
                    uint32_t b0h = W1h[bb], b1h = W1h[bb + 4];
                    uint32_t b0l = W1l[bb], b1l = W1l[bb + 4];
                    mma16816(acc[nt], ah, b0h, b1h);
                    mma16816(acc[nt], ah, b0l, b1l);
                    mma16816(acc[nt], al, b0h, b1h);
                }
            }
            #pragma unroll
            for (int nt = 0; nt < 2; nt++) {
                int col = n0base + nt * 8 + 2 * tg;
                float bb0 = sB[col], bb1 = sB[col + 1];
                uint32_t h, l;
                split2(silu_f(acc[nt][0] + bb0), silu_f(acc[nt][1] + bb1), h, l);
                A2h[(m0 + g) * 36 + (col >> 1)] = h;
                A2l[(m0 + g) * 36 + (col >> 1)] = l;
                split2(silu_f(acc[nt][2] + bb0), silu_f(acc[nt][3] + bb1), h, l);
                A2h[(m0 + g + 8) * 36 + (col >> 1)] = h;
                A2l[(m0 + g + 8) * 36 + (col >> 1)] = l;
            }
        }
        __syncthreads();

        // ================= layer 2: K=64 -> N=128, 4 n-tiles/warp ============
        {
            int n0base = nq * 32;
            float acc[4][4] = {};
            #pragma unroll
            for (int kt = 0; kt < 4; kt++) {
                uint32_t ah[4], al[4];
                int ab = (m0 + g) * 36 + kt * 8 + tg;
                ah[0] = A2h[ab]; ah[1] = A2h[ab + 288]; ah[2] = A2h[ab + 4]; ah[3] = A2h[ab + 292];
                al[0] = A2l[ab]; al[1] = A2l[ab + 288]; al[2] = A2l[ab + 4]; al[3] = A2l[ab + 292];
                #pragma unroll
                for (int nt = 0; nt < 4; nt++) {
                    int bb = (n0base + nt * 8 + g) * 36 + kt * 8 + tg;
                    uint32_t b0h = W2h[bb], b1h = W2h[bb + 4];
                    uint32_t b0l = W2l[bb], b1l = W2l[bb + 4];
                    mma16816(acc[nt], ah, b0h, b1h);
                    mma16816(acc[nt], ah, b0l, b1l);
                    mma16816(acc[nt], al, b0h, b1h);
                }
            }
            #pragma unroll
            for (int nt = 0; nt < 4; nt++) {
                int col = n0base + nt * 8 + 2 * tg;
                float bb0 = sB[64 + col], bb1 = sB[64 + col + 1];
                uint32_t h, l;
                split2(silu_f(acc[nt][0] + bb0), silu_f(acc[nt][1] + bb1), h, l);
                A3h[(m0 + g) * 68 + (col >> 1)] = h;
                A3l[(m0 + g) * 68 + (col >> 1)] = l;
                split2(silu_f(acc[nt][2] + bb0), silu_f(acc[nt][3] + bb1), h, l);
                A3h[(m0 + g + 8) * 68 + (col >> 1)] = h;
                A3l[(m0 + g + 8) * 68 + (col >> 1)] = l;
            }
        }
        __syncthreads();

        // ================= layer 3: K=128 -> N=192, 6 n-tiles/warp ===========
        {
            int n0base = nq * 48;
            float acc[6][4] = {};
            #pragma unroll
            for (int kt = 0; kt < 8; kt++) {
                uint32_t ah[4], al[4];
                int ab = (m0 + g) * 68 + kt * 8 + tg;
                ah[0] = A3h[ab]; ah[1] = A3h[ab + 544]; ah[2] = A3h[ab + 4]; ah[3] = A3h[ab + 548];
                al[0] = A3l[ab]; al[1] = A3l[ab + 544]; al[2] = A3l[ab + 4]; al[3] = A3l[ab + 548];
                #pragma unroll
                for (int nt = 0; nt < 6; nt++) {
                    int bb = (n0base + nt * 8 + g) * 68 + kt * 8 + tg;
                    uint32_t b0h = W3h[bb], b1h = W3h[bb + 4];
                    uint32_t b0l = W3l[bb], b1l = W3l[bb + 4];
                    mma16816(acc[nt], ah, b0h, b1h);
                    mma16816(acc[nt], ah, b0l, b1l);
                    mma16816(acc[nt], al, b0h, b1h);
                }
            }
            float w0 = ew[e0 + m0 + g];
            float w1 = ew[e0 + m0 + g + 8];
            float cw0 = 0.5f * (__cosf(w0 * (PI_F / 5.0f)) + 1.0f); cw0 = (w0 < 5.0f) ? cw0 : 0.0f;
            float cw1 = 0.5f * (__cosf(w1 * (PI_F / 5.0f)) + 1.0f); cw1 = (w1 < 5.0f) ? cw1 : 0.0f;
            float* o0 = g_a + (size_t)(e0 + m0 + g) * 192;
            float* o1 = g_a + (size_t)(e0 + m0 + g + 8) * 192;
            #pragma unroll
            for (int nt = 0; nt < 6; nt++) {
                int col = n0base + nt * 8 + 2 * tg;
                float bb0 = sB[192 + col], bb1 = sB[192 + col + 1];
                float2 v0 = make_float2(silu_f(acc[nt][0] + bb0) * cw0,
                                        silu_f(acc[nt][1] + bb1) * cw0);
                float2 v1 = make_float2(silu_f(acc[nt][2] + bb0) * cw1,
                                        silu_f(acc[nt][3] + bb1) * cw1);
                *(float2*)(o0 + col) = v0;
                *(float2*)(o1 + col) = v1;
            }
        }
        __syncthreads();
    }
}

// ---------------------------------------------------------------------------
// K3: message passing. Thread per (edge, channel).
// ---------------------------------------------------------------------------
__global__ __launch_bounds__(256) void k_message(const int* __restrict__ ei) {
    int idx = blockIdx.x * 256 + threadIdx.x;
    int e = idx >> 6, c = idx & 63;
    int src = __ldg(ei + e);
    int dst = __ldg(ei + Ee + e);
    const float* ap = g_a + (size_t)e * 192 + 3 * c;
    float aI = __ldg(ap), aA = __ldg(ap + 1), aS = __ldg(ap + 2);
    const float4* f = (const float4*)(g_feat + ((size_t)dst * 64 + c) * 12);
    float4 f0 = f[0], f1 = f[1];
    float  f8 = ((const float*)f)[8];
    float* b = g_msg + ((size_t)src * 64 + c) * 12;
    red4(b,     aI * f0.x, aA * f0.y, aA * f0.z, aA * f0.w);
    red4(b + 4, aS * f1.x, aS * f1.y, aS * f1.z, aS * f1.w);
    red1(b + 8, aS * f8);
}

// ---------------------------------------------------------------------------
// K4: finalize — 16 nodes/block, Wt[3..5] staged in smem.
// ---------------------------------------------------------------------------
__global__ __launch_bounds__(256) void k_finalize(const float* __restrict__ Wt,
                                                  float* __restrict__ out) {
    extern __shared__ float sm[];
    float* sw   = sm;            // Wt[3..5]
    float* sraw = sm + 12288;
    float* sdx  = sm + 21504;
    int t = threadIdx.x;
    int nb = blockIdx.x * 16;

    for (int i = t; i < 3072; i += 256)
        ((float4*)sw)[i] = ((const float4*)(Wt + 3 * 4096))[i];

    #pragma unroll
    for (int it = 0; it < 4; it++) {
        int p = t + it * 256;
        int s = p >> 6, c = p & 63;
        int n = nb + s;
        const float* mp = g_msg + ((size_t)n * 64 + c) * 12;
        const float* fp = g_feat + ((size_t)n * 64 + c) * 12;
        float mc[9], fc[9];
        #pragma unroll
        for (int i = 0; i < 9; i++) { mc[i] = mp[i]; fc[i] = fp[i]; }
        float Mg[9], Y[9];
        reconstruct(Mg, mc);
        reconstruct(Y, fc);
        float M1[9], M2[9], M[9];
        mm3(M1, Mg, Y);
        mm3(M2, Y, Mg);
        float nrm = 0.f;
        #pragma unroll
        for (int i = 0; i < 9; i++) { M[i] = M1[i] + M2[i]; nrm += M[i] * M[i]; }
        float inv = 1.f / (nrm + 1.f);
        float lam = (M[0] + M[4] + M[8]) * (1.f / 3.f);
        float* r = sraw + (s * 9) * 64 + c;
        r[0*64] = lam * inv;
        r[1*64] = 0.5f * (M[1] - M[3]) * inv;
        r[2*64] = 0.5f * (M[2] - M[6]) * inv;
        r[3*64] = 0.5f * (M[5] - M[7]) * inv;
        r[4*64] = (M[0] - lam) * inv;
        r[5*64] = (M[4] - lam) * inv;
        r[6*64] = 0.5f * (M[1] + M[3]) * inv;
        r[7*64] = 0.5f * (M[2] + M[6]) * inv;
        r[8*64] = 0.5f * (M[5] + M[7]) * inv;
    }
    __syncthreads();

    {
        int l = t & 63, g = t >> 6;
        #pragma unroll
        for (int comp = 0; comp < 9; comp++) {
            int sel = (comp == 0) ? 0 : ((comp < 4) ? 1 : 2);
            const float* w = sw + sel * 4096 + l;
            float a0 = 0.f, a1 = 0.f, a2 = 0.f, a3 = 0.f;
            const float* r0 = sraw + ((g*4 + 0) * 9 + comp) * 64;
            const float* r1 = sraw + ((g*4 + 1) * 9 + comp) * 64;
            const float* r2 = sraw + ((g*4 + 2) * 9 + comp) * 64;
            const float* r3 = sraw + ((g*4 + 3) * 9 + comp) * 64;
            #pragma unroll 16
            for (int k = 0; k < 64; k++) {
                float wv = w[k * 64];
                a0 = fmaf(r0[k], wv, a0);
                a1 = fmaf(r1[k], wv, a1);
                a2 = fmaf(r2[k], wv, a2);
                a3 = fmaf(r3[k], wv, a3);
            }
            sdx[((g*4 + 0) * 9 + comp) * 64 + l] = a0;
            sdx[((g*4 + 1) * 9 + comp) * 64 + l] = a1;
            sdx[((g*4 + 2) * 9 + comp) * 64 + l] = a2;
            sdx[((g*4 + 3) * 9 + comp) * 64 + l] = a3;
        }
    }
    __syncthreads();

    #pragma unroll
    for (int it = 0; it < 4; it++) {
        int p = t + it * 256;
        int s = p >> 6, c = p & 63;
        int n = nb + s;
        float dc[9];
        #pragma unroll
        for (int i = 0; i < 9; i++) dc[i] = sdx[(s * 9 + i) * 64 + c];
        float D[9];
        reconstruct(D, dc);
        float DD[9];
        mm3(DD, D, D);
        const float* xn = g_Xn + ((size_t)n * 64 + c) * 9;
        float* op = out + ((size_t)n * 64 + c) * 9;
        #pragma unroll
        for (int i = 0; i < 9; i++) op[i] = xn[i] + D[i] + DD[i];
    }
}

// ---------------------------------------------------------------------------
extern "C" void kernel_launch(void* const* d_in, const int* in_sizes, int n_in,
                              void* d_out, int out_size) {
    const float* X    = (const float*)d_in[0];
    const int*   ei   = (const int*)  d_in[1];
    const float* ew   = (const float*)d_in[2];
    const float* attr = (const float*)d_in[3];
    const float* W1   = (const float*)d_in[4];
    const float* b1   = (const float*)d_in[5];
    const float* W2   = (const float*)d_in[6];
    const float* b2   = (const float*)d_in[7];
    const float* W3   = (const float*)d_in[8];
    const float* b3   = (const float*)d_in[9];
    const float* Wt   = (const float*)d_in[10];
    float* out = (float*)d_out;

    // Idempotent, non-stream API calls — safe during graph capture, no static guard.
    cudaFuncSetAttribute(k_edge_mlp_mma, cudaFuncAttributeMaxDynamicSharedMemorySize,
                         EDGE_SMEM_BYTES);
    cudaFuncSetAttribute(k_nodeprep, cudaFuncAttributeMaxDynamicSharedMemorySize,
                         21504 * 4);
    cudaFuncSetAttribute(k_finalize, cudaFuncAttributeMaxDynamicSharedMemorySize,
                         30720 * 4);

    k_zero_msg<<<(Nn * Cc * 12 + 255) / 256, 256>>>();
    k_wprep<<<(34816 + 255) / 256, 256>>>(W1, W2, W3);
    k_nodeprep<<<Nn / 16, 256, 21504 * 4>>>(X, Wt);
    k_edge_mlp_mma<<<148, 512, EDGE_SMEM_BYTES>>>(attr, ew, b1, b2, b3);
    k_message<<<(Ee * Cc) / 256, 256>>>(ei);
    k_finalize<<<Nn / 16, 256, 30720 * 4>>>(Wt, out);
}

// round 13
// speedup vs baseline: 3.8172x; 1.0170x over previous
#include <cuda_runtime.h>
#include <cuda_bf16.h>
#include <cstdint>

#define Nn 10000
#define Ee 160000
#define Cc 64
#define PI_F 3.14159265358979f
#define NTILES 2500

// Scratch (global __device__ arrays)
__device__ float g_Xn  [Nn * Cc * 9];
__device__ float g_feat[Nn * Cc * 12];
__device__ float g_msg [Nn * Cc * 12];
__device__ float g_a   [(size_t)Ee * 192];

// Pre-transposed, padded bf16 hi/lo weights: [out][K+8] halves
__device__ __align__(16) __nv_bfloat16 g_W1h[64 * 40];
__device__ __align__(16) __nv_bfloat16 g_W1l[64 * 40];
__device__ __align__(16) __nv_bfloat16 g_W2h[128 * 72];
__device__ __align__(16) __nv_bfloat16 g_W2l[128 * 72];
__device__ __align__(16) __nv_bfloat16 g_W3h[192 * 136];
__device__ __align__(16) __nv_bfloat16 g_W3l[192 * 136];

__device__ __forceinline__ float silu_f(float x) {
    return x / (1.f + __expf(-x));
}

__device__ __forceinline__ void red4(float* p, float a, float b, float c, float d) {
    asm volatile("red.global.add.v4.f32 [%0], {%1,%2,%3,%4};"
                 :: "l"(p), "f"(a), "f"(b), "f"(c), "f"(d) : "memory");
}
__device__ __forceinline__ void red1(float* p, float a) {
    asm volatile("red.global.add.f32 [%0], %1;" :: "l"(p), "f"(a) : "memory");
}

__device__ __forceinline__ void reconstruct(float F[9], const float c[9]) {
    float lam = c[0], a01 = c[1], a02 = c[2], a12 = c[3];
    float s00 = c[4], s11 = c[5], s01 = c[6], s02 = c[7], s12 = c[8];
    float s22 = -(s00 + s11);
    F[0] = lam + s00;  F[1] =  a01 + s01; F[2] =  a02 + s02;
    F[3] = -a01 + s01; F[4] = lam + s11;  F[5] =  a12 + s12;
    F[6] = -a02 + s02; F[7] = -a12 + s12; F[8] = lam + s22;
}

__device__ __forceinline__ void mm3(float C[9], const float A[9], const float B[9]) {
    #pragma unroll
    for (int i = 0; i < 3; i++)
        #pragma unroll
        for (int j = 0; j < 3; j++) {
            float acc = 0.f;
            #pragma unroll
            for (int k = 0; k < 3; k++) acc += A[i*3+k] * B[k*3+j];
            C[i*3+j] = acc;
        }
}

// mma.m16n8k16 bf16, fp32 accumulate
__device__ __forceinline__ void mma16816(float* c, const uint32_t* a, uint32_t b0, uint32_t b1) {
    asm volatile(
        "mma.sync.aligned.m16n8k16.row.col.f32.bf16.bf16.f32 "
        "{%0,%1,%2,%3},{%4,%5,%6,%7},{%8,%9},{%0,%1,%2,%3};"
        : "+f"(c[0]), "+f"(c[1]), "+f"(c[2]), "+f"(c[3])
        : "r"(a[0]), "r"(a[1]), "r"(a[2]), "r"(a[3]), "r"(b0), "r"(b1));
}

// ldmatrix: 4x 8x8 b16 tiles (A operand m16k16)
__device__ __forceinline__ void ldsm_x4(uint32_t* r, uint32_t addr) {
    asm volatile("ldmatrix.sync.aligned.m8n8.x4.shared.b16 {%0,%1,%2,%3}, [%4];"
                 : "=r"(r[0]), "=r"(r[1]), "=r"(r[2]), "=r"(r[3]) : "r"(addr));
}
// ldmatrix: 2x 8x8 b16 tiles (B operand n8k16)
__device__ __forceinline__ void ldsm_x2(uint32_t& r0, uint32_t& r1, uint32_t addr) {
    asm volatile("ldmatrix.sync.aligned.m8n8.x2.shared.b16 {%0,%1}, [%2];"
                 : "=r"(r0), "=r"(r1) : "r"(addr));
}

// split (x0,x1) into packed bf16x2 hi and lo residual
__device__ __forceinline__ void split2(float x0, float x1, uint32_t& hi, uint32_t& lo) {
    __nv_bfloat162 h = __floats2bfloat162_rn(x0, x1);
    float r0 = x0 - __bfloat162float(h.x);
    float r1 = x1 - __bfloat162float(h.y);
    __nv_bfloat162 l = __floats2bfloat162_rn(r0, r1);
    hi = *(uint32_t*)&h;
    lo = *(uint32_t*)&l;
}

// ---------------------------------------------------------------------------
// K0: zero message accumulators
// ---------------------------------------------------------------------------
__global__ void k_zero_msg() {
    int i = blockIdx.x * 256 + threadIdx.x;
    if (i < Nn * Cc * 12) g_msg[i] = 0.f;
}

// ---------------------------------------------------------------------------
// KW: weight prep — transpose + pad + bf16 hi/lo split
// ---------------------------------------------------------------------------
__global__ void k_wprep(const float* __restrict__ W1, const float* __restrict__ W2,
                        const float* __restrict__ W3) {
    int idx = blockIdx.x * 256 + threadIdx.x;
    float w; __nv_bfloat16* ph; __nv_bfloat16* pl; int off;
    if (idx < 2048) {                 // W1: [32][64]
        int in = idx >> 6, out = idx & 63;
        w = W1[idx]; ph = g_W1h; pl = g_W1l; off = out * 40 + in;
    } else if (idx < 2048 + 8192) {   // W2: [64][128]
        int j = idx - 2048;
        int in = j >> 7, out = j & 127;
        w = W2[j]; ph = g_W2h; pl = g_W2l; off = out * 72 + in;
    } else if (idx < 2048 + 8192 + 24576) {  // W3: [128][192]
        int j = idx - 10240;
        int in = j / 192, out = j % 192;
        w = W3[j]; ph = g_W3h; pl = g_W3l; off = out * 136 + in;
    } else return;
    __nv_bfloat16 h = __float2bfloat16_rn(w);
    ph[off] = h;
    pl[off] = __float2bfloat16_rn(w - __bfloat162float(h));
}

// ---------------------------------------------------------------------------
// K1: node prep — 16 nodes/block, Wt[0..2] staged in smem.
// ---------------------------------------------------------------------------
__global__ __launch_bounds__(256) void k_nodeprep(const float* __restrict__ X,
                                                  const float* __restrict__ Wt) {
    extern __shared__ float sm[];
    float* sw   = sm;            // 3 * 4096
    float* sraw = sm + 12288;    // [16 nodes][9 comps][64 ch]
    int t = threadIdx.x;
    int nb = blockIdx.x * 16;

    for (int i = t; i < 3072; i += 256)
        ((float4*)sw)[i] = ((const float4*)Wt)[i];

    #pragma unroll
    for (int it = 0; it < 4; it++) {
        int p = t + it * 256;
        int s = p >> 6, c = p & 63;
        int n = nb + s;
        const float* xp = X + (size_t)(n * 64 + c) * 9;
        float x[9]; float n2 = 0.f;
        #pragma unroll
        for (int i = 0; i < 9; i++) { x[i] = xp[i]; n2 += x[i] * x[i]; }
        float inv = 1.f / (n2 + 1.f);
        float* xo = g_Xn + (size_t)(n * 64 + c) * 9;
        #pragma unroll
        for (int i = 0; i < 9; i++) { x[i] *= inv; xo[i] = x[i]; }
        float lam = (x[0] + x[4] + x[8]) * (1.f / 3.f);
        float* r = sraw + (s * 9) * 64 + c;
        r[0*64] = lam;
        r[1*64] = 0.5f * (x[1] - x[3]);
        r[2*64] = 0.5f * (x[2] - x[6]);
        r[3*64] = 0.5f * (x[5] - x[7]);
        r[4*64] = x[0] - lam;
        r[5*64] = x[4] - lam;
        r[6*64] = 0.5f * (x[1] + x[3]);
        r[7*64] = 0.5f * (x[2] + x[6]);
        r[8*64] = 0.5f * (x[5] + x[7]);
    }
    __syncthreads();

    int l = t & 63, g = t >> 6;           // g: 4 nodes each
    #pragma unroll
    for (int comp = 0; comp < 9; comp++) {
        int sel = (comp == 0) ? 0 : ((comp < 4) ? 1 : 2);
        const float* w = sw + sel * 4096 + l;
        float a0 = 0.f, a1 = 0.f, a2 = 0.f, a3 = 0.f;
        const float* r0 = sraw + ((g*4 + 0) * 9 + comp) * 64;
        const float* r1 = sraw + ((g*4 + 1) * 9 + comp) * 64;
        const float* r2 = sraw + ((g*4 + 2) * 9 + comp) * 64;
        const float* r3 = sraw + ((g*4 + 3) * 9 + comp) * 64;
        #pragma unroll 16
        for (int k = 0; k < 64; k++) {
            float wv = w[k * 64];
            a0 = fmaf(r0[k], wv, a0);
            a1 = fmaf(r1[k], wv, a1);
            a2 = fmaf(r2[k], wv, a2);
            a3 = fmaf(r3[k], wv, a3);
        }
        int n0 = nb + g * 4;
        g_feat[((size_t)(n0+0) * 64 + l) * 12 + comp] = a0;
        g_feat[((size_t)(n0+1) * 64 + l) * 12 + comp] = a1;
        g_feat[((size_t)(n0+2) * 64 + l) * 12 + comp] = a2;
        g_feat[((size_t)(n0+3) * 64 + l) * 12 + comp] = a3;
    }
}

// ---------------------------------------------------------------------------
// K2: edge MLP via mma.sync bf16 double-split, persistent blocks, ldmatrix.
// grid=148, 512 threads = 16 warps = 4 m-tiles x 4 n-quarters.
// ---------------------------------------------------------------------------
#define EOFF_W1H 0
#define EOFF_W1L 5120
#define EOFF_W2H 10240
#define EOFF_W2L 28672
#define EOFF_W3H 47104
#define EOFF_W3L 99328
#define EOFF_A1H 151552
#define EOFF_A1L 156672
#define EOFF_A2H 161792
#define EOFF_A2L 171008
#define EOFF_A3H 180224
#define EOFF_A3L 197632
#define EOFF_B   215040
#define EDGE_SMEM_BYTES 216576

__global__ __launch_bounds__(512) void k_edge_mlp_mma(
    const float* __restrict__ attr, const float* __restrict__ ew,
    const float* __restrict__ b1, const float* __restrict__ b2,
    const float* __restrict__ b3) {
    extern __shared__ __align__(16) uint8_t smraw[];
    uint32_t* A1h = (uint32_t*)(smraw + EOFF_A1H);
    uint32_t* A1l = (uint32_t*)(smraw + EOFF_A1L);
    uint32_t* A2h = (uint32_t*)(smraw + EOFF_A2H);
    uint32_t* A2l = (uint32_t*)(smraw + EOFF_A2L);
    uint32_t* A3h = (uint32_t*)(smraw + EOFF_A3H);
    uint32_t* A3l = (uint32_t*)(smraw + EOFF_A3L);
    float*    sB  = (float*)(smraw + EOFF_B);

    int t = threadIdx.x;
    uint32_t smbase = (uint32_t)__cvta_generic_to_shared(smraw);

    // ---- stage ALL weights once per block (persistent) ----
    for (int i = t; i < 320;  i += 512) ((uint4*)(smraw + EOFF_W1H))[i] = ((const uint4*)g_W1h)[i];
    for (int i = t; i < 320;  i += 512) ((uint4*)(smraw + EOFF_W1L))[i] = ((const uint4*)g_W1l)[i];
    for (int i = t; i < 1152; i += 512) ((uint4*)(smraw + EOFF_W2H))[i] = ((const uint4*)g_W2h)[i];
    for (int i = t; i < 1152; i += 512) ((uint4*)(smraw + EOFF_W2L))[i] = ((const uint4*)g_W2l)[i];
    for (int i = t; i < 3264; i += 512) ((uint4*)(smraw + EOFF_W3H))[i] = ((const uint4*)g_W3h)[i];
    for (int i = t; i < 3264; i += 512) ((uint4*)(smraw + EOFF_W3L))[i] = ((const uint4*)g_W3l)[i];
    for (int i = t; i < 384;  i += 512)
        sB[i] = (i < 64) ? b1[i] : (i < 192) ? b2[i - 64] : b3[i - 192];

    int lane = t & 31, wid = t >> 5;
    int g = lane >> 2, tg = lane & 3;
    int m0 = (wid & 3) * 16;          // 4 m-tiles of 16 edges
    int nq = wid >> 2;                // n-quarter 0..3

    // ldmatrix lane-address components
    int arow = lane & 15;             // A: row within 16-row tile
    int akoff = (lane >> 4) & 1;      // A: 0 -> k0-7 chunk, 1 -> k8-15 chunk (+16B)
    int brow = lane & 7;              // B: col within 8-col tile
    int bkoff = (lane >> 3) & 1;      // B: k-chunk select (+16B)

    for (int tidx = blockIdx.x; tidx < NTILES; tidx += gridDim.x) {
        int e0 = tidx * 64;

        // ---- stage attr -> A1 hi/lo bf16 (1024 pairs) ----
        #pragma unroll
        for (int i = 0; i < 2; i++) {
            int p = t + i * 512;
            int e = p >> 4, kp = p & 15;
            float2 x = *(const float2*)(attr + (size_t)(e0 + e) * 32 + kp * 2);
            uint32_t h, l;
            split2(x.x, x.y, h, l);
            A1h[e * 20 + kp] = h;
            A1l[e * 20 + kp] = l;
        }
        __syncthreads();

        // ================= layer 1: K=32 -> N=64, 2 n-tiles/warp =============
        {
            int n0base = nq * 16;
            float acc[2][4] = {};
            // pitch 80B
            uint32_t aAddrH = smbase + EOFF_A1H + (m0 + arow) * 80 + akoff * 16;
            uint32_t aAddrL = smbase + EOFF_A1L + (m0 + arow) * 80 + akoff * 16;
            #pragma unroll
            for (int kt = 0; kt < 2; kt++) {
                uint32_t ah[4], al[4];
                ldsm_x4(ah, aAddrH + kt * 32);
                ldsm_x4(al, aAddrL + kt * 32);
                #pragma unroll
                for (int nt = 0; nt < 2; nt++) {
                    uint32_t bOff = (n0base + nt * 8 + brow) * 80 + bkoff * 16 + kt * 32;
                    uint32_t b0h, b1h, b0l, b1l;
                    ldsm_x2(b0h, b1h, smbase + EOFF_W1H + bOff);
                    ldsm_x2(b0l, b1l, smbase + EOFF_W1L + bOff);
                    mma16816(acc[nt], ah, b0h, b1h);
                    mma16816(acc[nt], ah, b0l, b1l);
                    mma16816(acc[nt], al, b0h, b1h);
                }
            }
            #pragma unroll
            for (int nt = 0; nt < 2; nt++) {
                int col = n0base + nt * 8 + 2 * tg;
                float bb0 = sB[col], bb1 = sB[col + 1];
                uint32_t h, l;
                split2(silu_f(acc[nt][0] + bb0), silu_f(acc[nt][1] + bb1), h, l);
                A2h[(m0 + g) * 36 + (col >> 1)] = h;
                A2l[(m0 + g) * 36 + (col >> 1)] = l;
                split2(silu_f(acc[nt][2] + bb0), silu_f(acc[nt][3] + bb1), h, l);
                A2h[(m0 + g + 8) * 36 + (col >> 1)] = h;
                A2l[(m0 + g + 8) * 36 + (col >> 1)] = l;
            }
        }
        __syncthreads();

        // ================= layer 2: K=64 -> N=128, 4 n-tiles/warp ============
        {
            int n0base = nq * 32;
            float acc[4][4] = {};
            // pitch 144B
            uint32_t aAddrH = smbase + EOFF_A2H + (m0 + arow) * 144 + akoff * 16;
            uint32_t aAddrL = smbase + EOFF_A2L + (m0 + arow) * 144 + akoff * 16;
            #pragma unroll
            for (int kt = 0; kt < 4; kt++) {
                uint32_t ah[4], al[4];
                ldsm_x4(ah, aAddrH + kt * 32);
                ldsm_x4(al, aAddrL + kt * 32);
                #pragma unroll
                for (int nt = 0; nt < 4; nt++) {
                    uint32_t bOff = (n0base + nt * 8 + brow) * 144 + bkoff * 16 + kt * 32;
                    uint32_t b0h, b1h, b0l, b1l;
                    ldsm_x2(b0h, b1h, smbase + EOFF_W2H + bOff);
                    ldsm_x2(b0l, b1l, smbase + EOFF_W2L + bOff);
                    mma16816(acc[nt], ah, b0h, b1h);
                    mma16816(acc[nt], ah, b0l, b1l);
                    mma16816(acc[nt], al, b0h, b1h);
                }
            }
            #pragma unroll
            for (int nt = 0; nt < 4; nt++) {
                int col = n0base + nt * 8 + 2 * tg;
                float bb0 = sB[64 + col], bb1 = sB[64 + col + 1];
                uint32_t h, l;
                split2(silu_f(acc[nt][0] + bb0), silu_f(acc[nt][1] + bb1), h, l);
                A3h[(m0 + g) * 68 + (col >> 1)] = h;
                A3l[(m0 + g) * 68 + (col >> 1)] = l;
                split2(silu_f(acc[nt][2] + bb0), silu_f(acc[nt][3] + bb1), h, l);
                A3h[(m0 + g + 8) * 68 + (col >> 1)] = h;
                A3l[(m0 + g + 8) * 68 + (col >> 1)] = l;
            }
        }
        __syncthreads();

        // ================= layer 3: K=128 -> N=192, 6 n-tiles/warp ===========
        {
            int n0base = nq * 48;
            float acc[6][4] = {};
            // pitch 272B
            uint32_t aAddrH = smbase + EOFF_A3H + (m0 + arow) * 272 + akoff * 16;
            uint32_t aAddrL = smbase + EOFF_A3L + (m0 + arow) * 272 + akoff * 16;
            #pragma unroll
            for (int kt = 0; kt < 8; kt++) {
                uint32_t ah[4], al[4];
                ldsm_x4(ah, aAddrH + kt * 32);
                ldsm_x4(al, aAddrL + kt * 32);
                #pragma unroll
                for (int nt = 0; nt < 6; nt++) {
                    uint32_t bOff = (n0base + nt * 8 + brow) * 272 + bkoff * 16 + kt * 32;
                    uint32_t b0h, b1h, b0l, b1l;
                    ldsm_x2(b0h, b1h, smbase + EOFF_W3H + bOff);
                    ldsm_x2(b0l, b1l, smbase + EOFF_W3L + bOff);
                    mma16816(acc[nt], ah, b0h, b1h);
                    mma16816(acc[nt], ah, b0l, b1l);
                    mma16816(acc[nt], al, b0h, b1h);
                }
            }
            float w0 = ew[e0 + m0 + g];
            float w1 = ew[e0 + m0 + g + 8];
            float cw0 = 0.5f * (__cosf(w0 * (PI_F / 5.0f)) + 1.0f); cw0 = (w0 < 5.0f) ? cw0 : 0.0f;
            float cw1 = 0.5f * (__cosf(w1 * (PI_F / 5.0f)) + 1.0f); cw1 = (w1 < 5.0f) ? cw1 : 0.0f;
            float* o0 = g_a + (size_t)(e0 + m0 + g) * 192;
            float* o1 = g_a + (size_t)(e0 + m0 + g + 8) * 192;
            #pragma unroll
            for (int nt = 0; nt < 6; nt++) {
                int col = n0base + nt * 8 + 2 * tg;
                float bb0 = sB[192 + col], bb1 = sB[192 + col + 1];
                float2 v0 = make_float2(silu_f(acc[nt][0] + bb0) * cw0,
                                        silu_f(acc[nt][1] + bb1) * cw0);
                float2 v1 = make_float2(silu_f(acc[nt][2] + bb0) * cw1,
                                        silu_f(acc[nt][3] + bb1) * cw1);
                *(float2*)(o0 + col) = v0;
                *(float2*)(o1 + col) = v1;
            }
        }
        __syncthreads();
    }
}

// ---------------------------------------------------------------------------
// K3: message passing. Thread handles TWO independent (edge, channel) pairs
// for memory-level parallelism. grid = Ee*Cc/2/256.
// ---------------------------------------------------------------------------
__global__ __launch_bounds__(256) void k_message(const int* __restrict__ ei) {
    const int HALF = (Ee * Cc) / 2;
    int idx0 = blockIdx.x * 256 + threadIdx.x;
    int idx1 = idx0 + HALF;
    int e0 = idx0 >> 6, c0 = idx0 & 63;
    int e1 = idx1 >> 6, c1 = idx1 & 63;
    int s0 = __ldg(ei + e0), d0 = __ldg(ei + Ee + e0);
    int s1 = __ldg(ei + e1), d1 = __ldg(ei + Ee + e1);
    const float* ap0 = g_a + (size_t)e0 * 192 + 3 * c0;
    const float* ap1 = g_a + (size_t)e1 * 192 + 3 * c1;
    float aI0 = __ldg(ap0), aA0 = __ldg(ap0 + 1), aS0 = __ldg(ap0 + 2);
    float aI1 = __ldg(ap1), aA1 = __ldg(ap1 + 1), aS1 = __ldg(ap1 + 2);
    const float4* f0p = (const float4*)(g_feat + ((size_t)d0 * 64 + c0) * 12);
    const float4* f1p = (const float4*)(g_feat + ((size_t)d1 * 64 + c1) * 12);
    float4 f00 = f0p[0], f01 = f0p[1];
    float4 f10 = f1p[0], f11 = f1p[1];
    float  f08 = ((const float*)f0p)[8];
    float  f18 = ((const float*)f1p)[8];
    float* b0 = g_msg + ((size_t)s0 * 64 + c0) * 12;
    float* b1 = g_msg + ((size_t)s1 * 64 + c1) * 12;
    red4(b0,     aI0 * f00.x, aA0 * f00.y, aA0 * f00.z, aA0 * f00.w);
    red4(b1,     aI1 * f10.x, aA1 * f10.y, aA1 * f10.z, aA1 * f10.w);
    red4(b0 + 4, aS0 * f01.x, aS0 * f01.y, aS0 * f01.z, aS0 * f01.w);
    red4(b1 + 4, aS1 * f11.x, aS1 * f11.y, aS1 * f11.z, aS1 * f11.w);
    red1(b0 + 8, aS0 * f08);
    red1(b1 + 8, aS1 * f18);
}

// ---------------------------------------------------------------------------
// K4: finalize — 16 nodes/block, Wt[3..5] staged in smem.
// ---------------------------------------------------------------------------
__global__ __launch_bounds__(256) void k_finalize(const float* __restrict__ Wt,
                                                  float* __restrict__ out) {
    extern __shared__ float sm[];
    float* sw   = sm;            // Wt[3..5]
    float* sraw = sm + 12288;
    float* sdx  = sm + 21504;
    int t = threadIdx.x;
    int nb = blockIdx.x * 16;

    for (int i = t; i < 3072; i += 256)
        ((float4*)sw)[i] = ((const float4*)(Wt + 3 * 4096))[i];

    #pragma unroll
    for (int it = 0; it < 4; it++) {
        int p = t + it * 256;
        int s = p >> 6, c = p & 63;
        int n = nb + s;
        const float* mp = g_msg + ((size_t)n * 64 + c) * 12;
        const float* fp = g_feat + ((size_t)n * 64 + c) * 12;
        float mc[9], fc[9];
        #pragma unroll
        for (int i = 0; i < 9; i++) { mc[i] = mp[i]; fc[i] = fp[i]; }
        float Mg[9], Y[9];
        reconstruct(Mg, mc);
        reconstruct(Y, fc);
        float M1[9], M2[9], M[9];
        mm3(M1, Mg, Y);
        mm3(M2, Y, Mg);
        float nrm = 0.f;
        #pragma unroll
        for (int i = 0; i < 9; i++) { M[i] = M1[i] + M2[i]; nrm += M[i] * M[i]; }
        float inv = 1.f / (nrm + 1.f);
        float lam = (M[0] + M[4] + M[8]) * (1.f / 3.f);
        float* r = sraw + (s * 9) * 64 + c;
        r[0*64] = lam * inv;
        r[1*64] = 0.5f * (M[1] - M[3]) * inv;
        r[2*64] = 0.5f * (M[2] - M[6]) * inv;
        r[3*64] = 0.5f * (M[5] - M[7]) * inv;
        r[4*64] = (M[0] - lam) * inv;
        r[5*64] = (M[4] - lam) * inv;
        r[6*64] = 0.5f * (M[1] + M[3]) * inv;
        r[7*64] = 0.5f * (M[2] + M[6]) * inv;
        r[8*64] = 0.5f * (M[5] + M[7]) * inv;
    }
    __syncthreads();

    {
        int l = t & 63, g = t >> 6;
        #pragma unroll
        for (int comp = 0; comp < 9; comp++) {
            int sel = (comp == 0) ? 0 : ((comp < 4) ? 1 : 2);
            const float* w = sw + sel * 4096 + l;
            float a0 = 0.f, a1 = 0.f, a2 = 0.f, a3 = 0.f;
            const float* r0 = sraw + ((g*4 + 0) * 9 + comp) * 64;
            const float* r1 = sraw + ((g*4 + 1) * 9 + comp) * 64;
            const float* r2 = sraw + ((g*4 + 2) * 9 + comp) * 64;
            const float* r3 = sraw + ((g*4 + 3) * 9 + comp) * 64;
            #pragma unroll 16
            for (int k = 0; k < 64; k++) {
                float wv = w[k * 64];
                a0 = fmaf(r0[k], wv, a0);
                a1 = fmaf(r1[k], wv, a1);
                a2 = fmaf(r2[k], wv, a2);
                a3 = fmaf(r3[k], wv, a3);
            }
            sdx[((g*4 + 0) * 9 + comp) * 64 + l] = a0;
            sdx[((g*4 + 1) * 9 + comp) * 64 + l] = a1;
            sdx[((g*4 + 2) * 9 + comp) * 64 + l] = a2;
            sdx[((g*4 + 3) * 9 + comp) * 64 + l] = a3;
        }
    }
    __syncthreads();

    #pragma unroll
    for (int it = 0; it < 4; it++) {
        int p = t + it * 256;
        int s = p >> 6, c = p & 63;
        int n = nb + s;
        float dc[9];
        #pragma unroll
        for (int i = 0; i < 9; i++) dc[i] = sdx[(s * 9 + i) * 64 + c];
        float D[9];
        reconstruct(D, dc);
        float DD[9];
        mm3(DD, D, D);
        const float* xn = g_Xn + ((size_t)n * 64 + c) * 9;
        float* op = out + ((size_t)n * 64 + c) * 9;
        #pragma unroll
        for (int i = 0; i < 9; i++) op[i] = xn[i] + D[i] + DD[i];
    }
}

// ---------------------------------------------------------------------------
extern "C" void kernel_launch(void* const* d_in, const int* in_sizes, int n_in,
                              void* d_out, int out_size) {
    const float* X    = (const float*)d_in[0];
    const int*   ei   = (const int*)  d_in[1];
    const float* ew   = (const float*)d_in[2];
    const float* attr = (const float*)d_in[3];
    const float* W1   = (const float*)d_in[4];
    const float* b1   = (const float*)d_in[5];
    const float* W2   = (const float*)d_in[6];
    const float* b2   = (const float*)d_in[7];
    const float* W3   = (const float*)d_in[8];
    const float* b3   = (const float*)d_in[9];
    const float* Wt   = (const float*)d_in[10];
    float* out = (float*)d_out;

    // Idempotent, non-stream API calls — safe during graph capture, no static guard.
    cudaFuncSetAttribute(k_edge_mlp_mma, cudaFuncAttributeMaxDynamicSharedMemorySize,
                         EDGE_SMEM_BYTES);
    cudaFuncSetAttribute(k_nodeprep, cudaFuncAttributeMaxDynamicSharedMemorySize,
                         21504 * 4);
    cudaFuncSetAttribute(k_finalize, cudaFuncAttributeMaxDynamicSharedMemorySize,
                         30720 * 4);

    k_zero_msg<<<(Nn * Cc * 12 + 255) / 256, 256>>>();
    k_wprep<<<(34816 + 255) / 256, 256>>>(W1, W2, W3);
    k_nodeprep<<<Nn / 16, 256, 21504 * 4>>>(X, Wt);
    k_edge_mlp_mma<<<148, 512, EDGE_SMEM_BYTES>>>(attr, ew, b1, b2, b3);
    k_message<<<(Ee * Cc / 2) / 256, 256>>>(ei);
    k_finalize<<<Nn / 16, 256, 30720 * 4>>>(Wt, out);
}